// round 11
// baseline (speedup 1.0000x reference)
#include <cuda_runtime.h>
#include <cuda_fp16.h>
#include <cstdint>

// Fixed problem shape
#define NB   4
#define SEQ  2048
#define EMB  1024
#define HEADS 16
#define DH   64
#define NH   (NB * HEADS)
#define ROWS_TOT (NB * SEQ * HEADS)   // 131072

// Scratch (device globals), all fp16.
// g_q/g_k: (n,s,h,d). g_v: (n,h,d,s) = pre-transposed for PV B-fragments.
// g_ao: (n,q,h,d). g_wo: Wo TRANSPOSED [j][k].
__device__ __half g_q[ROWS_TOT * DH];
__device__ __half g_k[ROWS_TOT * DH];
__device__ __half g_v[ROWS_TOT * DH];
__device__ __half g_ao[NB * SEQ * EMB];
__device__ __half g_wo[EMB * EMB];

// ===========================================================================
// helpers
// ===========================================================================
__device__ __forceinline__ uint32_t h2pack(float lo, float hi) {
    uint32_t r;
    asm("cvt.rn.f16x2.f32 %0, %1, %2;" : "=r"(r) : "f"(hi), "f"(lo));
    return r;
}
__device__ __forceinline__ void mma_f16(float* d, const uint32_t* a,
                                        uint32_t b0, uint32_t b1) {
    asm volatile(
        "mma.sync.aligned.m16n8k16.row.col.f32.f16.f16.f32 "
        "{%0,%1,%2,%3}, {%4,%5,%6,%7}, {%8,%9}, {%0,%1,%2,%3};"
        : "+f"(d[0]), "+f"(d[1]), "+f"(d[2]), "+f"(d[3])
        : "r"(a[0]), "r"(a[1]), "r"(a[2]), "r"(a[3]), "r"(b0), "r"(b1));
}
__device__ __forceinline__ uint32_t smem_u32(const void* p) {
    uint32_t a;
    asm("{ .reg .u64 t; cvta.to.shared.u64 t, %1; cvt.u32.u64 %0, t; }"
        : "=r"(a) : "l"(p));
    return a;
}
__device__ __forceinline__ void cp16(uint32_t dst, const void* src) {
    asm volatile("cp.async.cg.shared.global [%0], [%1], 16;"
                 :: "r"(dst), "l"(src) : "memory");
}
#define CP_COMMIT() asm volatile("cp.async.commit_group;" ::: "memory")
#define CP_WAIT0()  asm volatile("cp.async.wait_group 0;" ::: "memory")
#define CP_WAIT1()  asm volatile("cp.async.wait_group 1;" ::: "memory")

// ---------------------------------------------------------------------------
// Kernel 0: transpose Wo -> g_wo[j][k] as half
// ---------------------------------------------------------------------------
__global__ void __launch_bounds__(256) wo_cvt(const float* __restrict__ Wo) {
    __shared__ float tile[32][33];
    const int j0 = blockIdx.x * 32, k0 = blockIdx.y * 32;
    const int tx = threadIdx.x & 31, ty = threadIdx.x >> 5;   // ty 0..7
#pragma unroll
    for (int i = 0; i < 4; i++)
        tile[ty + 8 * i][tx] = Wo[(k0 + ty + 8 * i) * EMB + j0 + tx];
    __syncthreads();
#pragma unroll
    for (int i = 0; i < 4; i++)
        g_wo[(j0 + ty + 8 * i) * EMB + k0 + tx] = __float2half_rn(tile[tx][ty + 8 * i]);
}

// ---------------------------------------------------------------------------
// Kernel 1: per-head projections on HMMA fp16. 128 rows/block, 4 warps.
// Outputs: q/k (n,s,h,d) half; v (n,h,d,s) half (transposed for flash PV).
// ---------------------------------------------------------------------------
__global__ void __launch_bounds__(128) proj_mma(
    const float* __restrict__ vals, const float* __restrict__ keys,
    const float* __restrict__ qry,
    const float* __restrict__ Wv, const float* __restrict__ Wk,
    const float* __restrict__ Wq)
{
    __shared__ __align__(16) __half Xh[128 * 72];   // X tile [r][d]
    __shared__ __align__(16) __half Wh[64 * 72];    // W transposed [c][d]

    const int t = blockIdx.y;
    const float* X = (t == 0) ? vals : (t == 1) ? keys : qry;
    const float* W = (t == 0) ? Wv   : (t == 1) ? Wk   : Wq;
    const float scale = (t == 2) ? 0.03125f : 1.0f;

    const int tid = threadIdx.x;
    const int wid = tid >> 5, lane = tid & 31;
    const int gp = lane >> 2, tg = lane & 3;
    const int g0 = blockIdx.x * 128;
    const int wr = wid * 32;

    for (int i = tid; i < 4096; i += 128) {
        int d = i >> 6, c = i & 63;
        Wh[c * 72 + d] = __float2half_rn(W[i]);
    }
    for (int idx = tid * 4; idx < 128 * 64; idx += 512) {
        int r = idx >> 6, d = idx & 63;
        float4 v = *(const float4*)&X[(g0 + r) * 64 + d];
        *(uint32_t*)&Xh[r * 72 + d]     = h2pack(v.x * scale, v.y * scale);
        *(uint32_t*)&Xh[r * 72 + d + 2] = h2pack(v.z * scale, v.w * scale);
    }
    __syncthreads();

    float acc[2][8][4] = {};
#pragma unroll
    for (int kc = 0; kc < 4; kc++) {
        const int k0 = kc * 16 + 2 * tg;
        uint32_t a[2][4];
#pragma unroll
        for (int mt = 0; mt < 2; mt++) {
            const int rr = wr + mt * 16 + gp;
            a[mt][0] = *(uint32_t*)&Xh[rr * 72 + k0];
            a[mt][1] = *(uint32_t*)&Xh[(rr + 8) * 72 + k0];
            a[mt][2] = *(uint32_t*)&Xh[rr * 72 + k0 + 8];
            a[mt][3] = *(uint32_t*)&Xh[(rr + 8) * 72 + k0 + 8];
        }
#pragma unroll
        for (int nt = 0; nt < 8; nt++) {
            const uint32_t b0 = *(uint32_t*)&Wh[(nt * 8 + gp) * 72 + k0];
            const uint32_t b1 = *(uint32_t*)&Wh[(nt * 8 + gp) * 72 + k0 + 8];
            mma_f16(acc[0][nt], a[0], b0, b1);
            mma_f16(acc[1][nt], a[1], b0, b1);
        }
    }
    __syncthreads();   // Xh free for epilogue reuse

    if (t != 0) {
        // q/k: smem-transpose to [r][c], then fully linear 16B writes
        __half* out = (t == 1) ? g_k : g_q;
#pragma unroll
        for (int mt = 0; mt < 2; mt++) {
            const int rr = wr + mt * 16 + gp;
#pragma unroll
            for (int nt = 0; nt < 8; nt++) {
                const int c = nt * 8 + 2 * tg;
                *(uint32_t*)&Xh[rr * 72 + c]       = h2pack(acc[mt][nt][0], acc[mt][nt][1]);
                *(uint32_t*)&Xh[(rr + 8) * 72 + c] = h2pack(acc[mt][nt][2], acc[mt][nt][3]);
            }
        }
        __syncthreads();
        for (int i = tid; i < 1024; i += 128) {
            int r = i >> 3, c8 = (i & 7) * 8;
            *(uint4*)&out[(size_t)(g0 + r) * 64 + c8] = *(uint4*)&Xh[r * 72 + c8];
        }
    } else {
        // v: transpose to (h,d,s-local) in smem, then 16B chunks to (n,h,d,s)
        __half* vsm = Xh;   // 16 * 64 * 8 = 8192 halves
#pragma unroll
        for (int mt = 0; mt < 2; mt++) {
#pragma unroll
            for (int nt = 0; nt < 8; nt++) {
                const int c = nt * 8 + 2 * tg;
                const int r0r = wr + mt * 16 + gp;
                const int r1r = r0r + 8;
                vsm[((r0r & 15) * 64 + c)     * 8 + (r0r >> 4)] = __float2half_rn(acc[mt][nt][0]);
                vsm[((r0r & 15) * 64 + c + 1) * 8 + (r0r >> 4)] = __float2half_rn(acc[mt][nt][1]);
                vsm[((r1r & 15) * 64 + c)     * 8 + (r1r >> 4)] = __float2half_rn(acc[mt][nt][2]);
                vsm[((r1r & 15) * 64 + c + 1) * 8 + (r1r >> 4)] = __float2half_rn(acc[mt][nt][3]);
            }
        }
        __syncthreads();
        const int n = g0 >> 15;
        const int s0 = (g0 >> 4) & (SEQ - 1);
        for (int i = tid; i < 1024; i += 128) {
            int h = i >> 6, d = i & 63;
            *(uint4*)&g_v[(size_t)((n * 16 + h) * 64 + d) * SEQ + s0] =
                *(uint4*)&vsm[(h * 64 + d) * 8];
        }
    }
}

// ---------------------------------------------------------------------------
// Kernel 2: flash attention on fp16 HMMA. BQ=256: 256 threads, 8 warps x 32
// q-rows (per-warp fragment layout identical to R10). Halves K/V L2 re-reads
// and syncs per FLOP. Q stages into the combined K+V buffer region (exact fit);
// epilogue reuses it too. P entirely in registers.
// ---------------------------------------------------------------------------
__global__ void __launch_bounds__(256, 1) flash_mma(const float* __restrict__ mask)
{
    __shared__ __align__(16) __half Sh[18432];   // [0,9216): K bufs [2][64][72]
                                                 // [9216,18432): V bufs [2][64][72]
    __shared__ float msf[SEQ];                   // mask bias

    const int tid = threadIdx.x;
    const int wid = tid >> 5, lane = tid & 31;
    const int gp = lane >> 2, tg = lane & 3;
    const int bh = blockIdx.y;
    const int n = bh >> 4, h = bh & 15;
    const int q0 = blockIdx.x * 256;
    const size_t base0 = ((size_t)n << 21) | (size_t)(h << 6);   // +s*1024+d
    const size_t vbase = (size_t)(n * 16 + h) * 64 * SEQ;        // +d*2048+s

    // stage Q tile (256 rows x 64 cols, stride 72 -> exactly fills Sh)
    for (int i = tid; i < 2048; i += 256) {
        int r = i >> 3, c8 = (i & 7) * 8;
        cp16(smem_u32(&Sh[r * 72 + c8]), g_q + base0 + (size_t)(q0 + r) * 1024 + c8);
    }
    CP_COMMIT();
    for (int i = tid; i < SEQ; i += 256)
        msf[i] = (mask[n * SEQ + i] == 0.0f) ? -1.0e30f : 0.0f;
    CP_WAIT0();
    __syncthreads();

    // Q fragments (m16n8k16 A): 4 k-chunks x 2 mt x 4 regs; rows wid*32+...
    uint32_t qf[4][2][4];
#pragma unroll
    for (int kc = 0; kc < 4; kc++) {
        const int k0 = kc * 16 + 2 * tg;
#pragma unroll
        for (int mt = 0; mt < 2; mt++) {
            const int rr = wid * 32 + mt * 16 + gp;
            qf[kc][mt][0] = *(uint32_t*)&Sh[rr * 72 + k0];
            qf[kc][mt][1] = *(uint32_t*)&Sh[(rr + 8) * 72 + k0];
            qf[kc][mt][2] = *(uint32_t*)&Sh[rr * 72 + k0 + 8];
            qf[kc][mt][3] = *(uint32_t*)&Sh[(rr + 8) * 72 + k0 + 8];
        }
    }
    __syncthreads();

    // prefetch K/V tile 0 into buf 0
    for (int i = tid; i < 1024; i += 256) {
        if (i < 512) {
            int r = i >> 3, c8 = (i & 7) * 8;
            cp16(smem_u32(&Sh[r * 72 + c8]), g_k + base0 + (size_t)r * 1024 + c8);
        } else {
            int d = (i - 512) >> 3, s8 = ((i - 512) & 7) * 8;
            cp16(smem_u32(&Sh[9216 + d * 72 + s8]), g_v + vbase + (size_t)d * SEQ + s8);
        }
    }
    CP_COMMIT();

    float ofrag[2][8][4] = {};
    float lsum[2][2] = {};

    for (int kt = 0; kt < 32; kt++) {
        if (kt + 1 < 32) {
            const int buf = (kt + 1) & 1;
            for (int i = tid; i < 1024; i += 256) {
                if (i < 512) {
                    int r = i >> 3, c8 = (i & 7) * 8;
                    cp16(smem_u32(&Sh[buf * 4608 + r * 72 + c8]),
                         g_k + base0 + (size_t)((kt + 1) * 64 + r) * 1024 + c8);
                } else {
                    int d = (i - 512) >> 3, s8 = ((i - 512) & 7) * 8;
                    cp16(smem_u32(&Sh[9216 + buf * 4608 + d * 72 + s8]),
                         g_v + vbase + (size_t)d * SEQ + (kt + 1) * 64 + s8);
                }
            }
            CP_COMMIT();
            CP_WAIT1();
        } else {
            CP_WAIT0();
        }
        __syncthreads();

        const __half* Kb = Sh + (kt & 1) * 4608;
        const __half* Vb = Sh + 9216 + (kt & 1) * 4608;

        // S = Q @ K^T  (32 x 64 per warp, 4 k-chunks of 16)
        float sf[2][8][4] = {};
#pragma unroll
        for (int kc = 0; kc < 4; kc++) {
            const int k0 = kc * 16 + 2 * tg;
#pragma unroll
            for (int nt = 0; nt < 8; nt++) {
                const uint32_t b0 = *(uint32_t*)&Kb[(nt * 8 + gp) * 72 + k0];
                const uint32_t b1 = *(uint32_t*)&Kb[(nt * 8 + gp) * 72 + k0 + 8];
                mma_f16(sf[0][nt], qf[kc][0], b0, b1);
                mma_f16(sf[1][nt], qf[kc][1], b0, b1);
            }
        }

        // softmax in regs; pack C-frag pairs directly into PV A-frags
        uint32_t pa[2][4][4];
#pragma unroll
        for (int mt = 0; mt < 2; mt++) {
#pragma unroll
            for (int nt = 0; nt < 8; nt++) {
                const int c0 = nt * 8 + 2 * tg;
                const float mb0 = msf[kt * 64 + c0];
                const float mb1 = msf[kt * 64 + c0 + 1];
                float p0 = __expf(sf[mt][nt][0] + mb0);
                float p1 = __expf(sf[mt][nt][1] + mb1);
                float p2 = __expf(sf[mt][nt][2] + mb0);
                float p3 = __expf(sf[mt][nt][3] + mb1);
                lsum[mt][0] += p0 + p1;
                lsum[mt][1] += p2 + p3;
                const int j = nt >> 1;
                if ((nt & 1) == 0) {
                    pa[mt][j][0] = h2pack(p0, p1);
                    pa[mt][j][1] = h2pack(p2, p3);
                } else {
                    pa[mt][j][2] = h2pack(p0, p1);
                    pa[mt][j][3] = h2pack(p2, p3);
                }
            }
        }

        // O += P @ V  (V in smem as [d][s] -> B-frags are contiguous half2)
#pragma unroll
        for (int j = 0; j < 4; j++) {
            const int k0 = j * 16 + 2 * tg;
#pragma unroll
            for (int nt = 0; nt < 8; nt++) {
                const uint32_t b0 = *(uint32_t*)&Vb[(nt * 8 + gp) * 72 + k0];
                const uint32_t b1 = *(uint32_t*)&Vb[(nt * 8 + gp) * 72 + k0 + 8];
                mma_f16(ofrag[0][nt], pa[0][j], b0, b1);
                mma_f16(ofrag[1][nt], pa[1][j], b0, b1);
            }
        }
        __syncthreads();
    }

    // reduce row sums across the 4 tg threads (cols spread over tg)
#pragma unroll
    for (int mt = 0; mt < 2; mt++)
#pragma unroll
        for (int rh = 0; rh < 2; rh++) {
            lsum[mt][rh] += __shfl_xor_sync(0xffffffffu, lsum[mt][rh], 1);
            lsum[mt][rh] += __shfl_xor_sync(0xffffffffu, lsum[mt][rh], 2);
        }

    // epilogue: normalize -> half, per-warp smem transpose, linear 16B stores
    __half* aobuf = Sh + wid * 2304;   // 32 x 72 halves per warp (8 x 2304 = fit)
#pragma unroll
    for (int mt = 0; mt < 2; mt++) {
        const float inv0 = 1.0f / lsum[mt][0];
        const float inv1 = 1.0f / lsum[mt][1];
        const int rr = mt * 16 + gp;
#pragma unroll
        for (int nt = 0; nt < 8; nt++) {
            const int c = nt * 8 + 2 * tg;
            *(uint32_t*)&aobuf[rr * 72 + c] =
                h2pack(ofrag[mt][nt][0] * inv0, ofrag[mt][nt][1] * inv0);
            *(uint32_t*)&aobuf[(rr + 8) * 72 + c] =
                h2pack(ofrag[mt][nt][2] * inv1, ofrag[mt][nt][3] * inv1);
        }
    }
    __syncwarp();
    const size_t obase = (size_t)(n * SEQ + q0 + wid * 32) * 1024 + h * 64;
    for (int i = lane; i < 256; i += 32) {
        int r = i >> 3, c8 = (i & 7) * 8;
        *(uint4*)&g_ao[obase + (size_t)r * 1024 + c8] = *(uint4*)&aobuf[r * 72 + c8];
    }
}

// ---------------------------------------------------------------------------
// Kernel 3: out = g_ao @ Wo + bo on fp16 HMMA. 128 threads, 4 warps (2x2),
// warp tile 64x64, BK=32 (2 k-chunks of 16). cp.async double-buffered.
// ---------------------------------------------------------------------------
#define OG_SMEM 71680   // staging 40960B (half) + epilogue float reuse

__global__ void __launch_bounds__(128, 2) out_gemm(
    const float* __restrict__ bo, float* __restrict__ out)
{
    extern __shared__ __align__(16) char og[];
    __half* Ash = (__half*)og;            // [2][128][40]
    __half* Bsh = Ash + 10240;            // [2][128][40]

    const int tid = threadIdx.x;
    const int wid = tid >> 5, lane = tid & 31;
    const int gp = lane >> 2, tg = lane & 3;
    const int wr = (wid & 1) * 64;
    const int wc = (wid >> 1) * 64;
    const int j0 = blockIdx.x * 128;
    const int m0 = blockIdx.y * 128;

    float acc[4][8][4] = {};

    for (int i = tid; i < 1024; i += 128) {
        if (i < 512) {
            int r = i >> 2, c8 = (i & 3) * 8;
            cp16(smem_u32(&Ash[r * 40 + c8]), g_ao + (size_t)(m0 + r) * 1024 + c8);
        } else {
            int r = (i - 512) >> 2, c8 = ((i - 512) & 3) * 8;
            cp16(smem_u32(&Bsh[r * 40 + c8]), g_wo + (size_t)(j0 + r) * 1024 + c8);
        }
    }
    CP_COMMIT();

    for (int kt = 0; kt < 32; kt++) {
        if (kt + 1 < 32) {
            const int buf = (kt + 1) & 1;
            const int k0g = (kt + 1) * 32;
            for (int i = tid; i < 1024; i += 128) {
                if (i < 512) {
                    int r = i >> 2, c8 = (i & 3) * 8;
                    cp16(smem_u32(&Ash[buf * 5120 + r * 40 + c8]),
                         g_ao + (size_t)(m0 + r) * 1024 + k0g + c8);
                } else {
                    int r = (i - 512) >> 2, c8 = ((i - 512) & 3) * 8;
                    cp16(smem_u32(&Bsh[buf * 5120 + r * 40 + c8]),
                         g_wo + (size_t)(j0 + r) * 1024 + k0g + c8);
                }
            }
            CP_COMMIT();
            CP_WAIT1();
        } else {
            CP_WAIT0();
        }
        __syncthreads();

        const __half* Ab = Ash + (kt & 1) * 5120;
        const __half* Bb = Bsh + (kt & 1) * 5120;
#pragma unroll
        for (int kc = 0; kc < 2; kc++) {
            const int k0 = kc * 16 + 2 * tg;
            uint32_t a[4][4];
#pragma unroll
            for (int mt = 0; mt < 4; mt++) {
                const int rr = wr + mt * 16 + gp;
                a[mt][0] = *(uint32_t*)&Ab[rr * 40 + k0];
                a[mt][1] = *(uint32_t*)&Ab[(rr + 8) * 40 + k0];
                a[mt][2] = *(uint32_t*)&Ab[rr * 40 + k0 + 8];
                a[mt][3] = *(uint32_t*)&Ab[(rr + 8) * 40 + k0 + 8];
            }
#pragma unroll
            for (int nt = 0; nt < 8; nt++) {
                const uint32_t b0 = *(uint32_t*)&Bb[(wc + nt * 8 + gp) * 40 + k0];
                const uint32_t b1 = *(uint32_t*)&Bb[(wc + nt * 8 + gp) * 40 + k0 + 8];
                mma_f16(acc[0][nt], a[0], b0, b1);
                mma_f16(acc[1][nt], a[1], b0, b1);
                mma_f16(acc[2][nt], a[2], b0, b1);
                mma_f16(acc[3][nt], a[3], b0, b1);
            }
        }
        __syncthreads();
    }

    // epilogue: bias + smem-transpose per warp (64x68 f32), linear stores
    float* sf = (float*)og + wid * 4352;
#pragma unroll
    for (int mt = 0; mt < 4; mt++) {
        const int rr = mt * 16 + gp;
#pragma unroll
        for (int nt = 0; nt < 8; nt++) {
            const int cc = nt * 8 + 2 * tg;
            const float b0v = bo[j0 + wc + cc];
            const float b1v = bo[j0 + wc + cc + 1];
            sf[rr * 68 + cc]           = acc[mt][nt][0] + b0v;
            sf[rr * 68 + cc + 1]       = acc[mt][nt][1] + b1v;
            sf[(rr + 8) * 68 + cc]     = acc[mt][nt][2] + b0v;
            sf[(rr + 8) * 68 + cc + 1] = acc[mt][nt][3] + b1v;
        }
    }
    __syncwarp();
    const size_t obase = (size_t)(m0 + wr) * 1024 + j0 + wc;
    for (int i = lane; i < 1024; i += 32) {
        int r = i >> 4, c4 = (i & 15) * 4;
        *(float4*)&out[obase + (size_t)r * 1024 + c4] = *(float4*)&sf[r * 68 + c4];
    }
}

// ---------------------------------------------------------------------------
extern "C" void kernel_launch(void* const* d_in, const int* in_sizes, int n_in,
                              void* d_out, int out_size)
{
    const float* values = (const float*)d_in[0];
    const float* keys   = (const float*)d_in[1];
    const float* query  = (const float*)d_in[2];
    const float* mask   = (const float*)d_in[3];
    const float* Wv     = (const float*)d_in[4];
    const float* Wk     = (const float*)d_in[5];
    const float* Wq     = (const float*)d_in[6];
    const float* Wo     = (const float*)d_in[7];
    const float* bo     = (const float*)d_in[8];
    float* out = (float*)d_out;

    cudaFuncSetAttribute(out_gemm, cudaFuncAttributeMaxDynamicSharedMemorySize, OG_SMEM);

    proj_mma<<<dim3(ROWS_TOT / 128, 3), 128>>>(values, keys, query, Wv, Wk, Wq);
    wo_cvt<<<dim3(32, 32), 256>>>(Wo);
    flash_mma<<<dim3(SEQ / 256, NH), 256>>>(mask);
    out_gemm<<<dim3(EMB / 128, (NB * SEQ) / 128), 128, OG_SMEM>>>(bo, out);
}

// round 12
// speedup vs baseline: 1.1872x; 1.1872x over previous
#include <cuda_runtime.h>
#include <cuda_fp16.h>
#include <cstdint>

// Fixed problem shape
#define NB   4
#define SEQ  2048
#define EMB  1024
#define HEADS 16
#define DH   64
#define NH   (NB * HEADS)
#define ROWS_TOT (NB * SEQ * HEADS)   // 131072

// Scratch (device globals), all fp16.
// g_q/g_k: (n,s,h,d). g_v: (n,h,d,s) = pre-transposed for PV B-fragments.
// g_ao: (n,q,h,d). g_wo: Wo TRANSPOSED [j][k].
__device__ __half g_q[ROWS_TOT * DH];
__device__ __half g_k[ROWS_TOT * DH];
__device__ __half g_v[ROWS_TOT * DH];
__device__ __half g_ao[NB * SEQ * EMB];
__device__ __half g_wo[EMB * EMB];

#define HALF2_ONES 0x3C003C00u   // (1.0h, 1.0h)

// ===========================================================================
// helpers
// ===========================================================================
__device__ __forceinline__ uint32_t h2pack(float lo, float hi) {
    uint32_t r;
    asm("cvt.rn.f16x2.f32 %0, %1, %2;" : "=r"(r) : "f"(hi), "f"(lo));
    return r;
}
__device__ __forceinline__ uint32_t ex2h2(uint32_t x) {
    uint32_t r;
    asm("ex2.approx.f16x2 %0, %1;" : "=r"(r) : "r"(x));
    return r;
}
__device__ __forceinline__ void mma_f16(float* d, const uint32_t* a,
                                        uint32_t b0, uint32_t b1) {
    asm volatile(
        "mma.sync.aligned.m16n8k16.row.col.f32.f16.f16.f32 "
        "{%0,%1,%2,%3}, {%4,%5,%6,%7}, {%8,%9}, {%0,%1,%2,%3};"
        : "+f"(d[0]), "+f"(d[1]), "+f"(d[2]), "+f"(d[3])
        : "r"(a[0]), "r"(a[1]), "r"(a[2]), "r"(a[3]), "r"(b0), "r"(b1));
}
__device__ __forceinline__ uint32_t smem_u32(const void* p) {
    uint32_t a;
    asm("{ .reg .u64 t; cvta.to.shared.u64 t, %1; cvt.u32.u64 %0, t; }"
        : "=r"(a) : "l"(p));
    return a;
}
__device__ __forceinline__ void cp16(uint32_t dst, const void* src) {
    asm volatile("cp.async.cg.shared.global [%0], [%1], 16;"
                 :: "r"(dst), "l"(src) : "memory");
}
#define CP_COMMIT() asm volatile("cp.async.commit_group;" ::: "memory")
#define CP_WAIT0()  asm volatile("cp.async.wait_group 0;" ::: "memory")
#define CP_WAIT1()  asm volatile("cp.async.wait_group 1;" ::: "memory")

// ---------------------------------------------------------------------------
// Kernel 0: transpose Wo -> g_wo[j][k] as half
// ---------------------------------------------------------------------------
__global__ void __launch_bounds__(256) wo_cvt(const float* __restrict__ Wo) {
    __shared__ float tile[32][33];
    const int j0 = blockIdx.x * 32, k0 = blockIdx.y * 32;
    const int tx = threadIdx.x & 31, ty = threadIdx.x >> 5;   // ty 0..7
#pragma unroll
    for (int i = 0; i < 4; i++)
        tile[ty + 8 * i][tx] = Wo[(k0 + ty + 8 * i) * EMB + j0 + tx];
    __syncthreads();
#pragma unroll
    for (int i = 0; i < 4; i++)
        g_wo[(j0 + ty + 8 * i) * EMB + k0 + tx] = __float2half_rn(tile[tx][ty + 8 * i]);
}

// ---------------------------------------------------------------------------
// Kernel 1: per-head projections on HMMA fp16. 128 rows/block, 4 warps.
// Outputs: q/k (n,s,h,d) half; v (n,h,d,s) half (transposed for flash PV).
// ---------------------------------------------------------------------------
__global__ void __launch_bounds__(128) proj_mma(
    const float* __restrict__ vals, const float* __restrict__ keys,
    const float* __restrict__ qry,
    const float* __restrict__ Wv, const float* __restrict__ Wk,
    const float* __restrict__ Wq)
{
    __shared__ __align__(16) __half Xh[128 * 72];   // X tile [r][d]
    __shared__ __align__(16) __half Wh[64 * 72];    // W transposed [c][d]

    const int t = blockIdx.y;
    const float* X = (t == 0) ? vals : (t == 1) ? keys : qry;
    const float* W = (t == 0) ? Wv   : (t == 1) ? Wk   : Wq;
    const float scale = (t == 2) ? 0.03125f : 1.0f;

    const int tid = threadIdx.x;
    const int wid = tid >> 5, lane = tid & 31;
    const int gp = lane >> 2, tg = lane & 3;
    const int g0 = blockIdx.x * 128;
    const int wr = wid * 32;

    for (int i = tid; i < 4096; i += 128) {
        int d = i >> 6, c = i & 63;
        Wh[c * 72 + d] = __float2half_rn(W[i]);
    }
    for (int idx = tid * 4; idx < 128 * 64; idx += 512) {
        int r = idx >> 6, d = idx & 63;
        float4 v = *(const float4*)&X[(g0 + r) * 64 + d];
        *(uint32_t*)&Xh[r * 72 + d]     = h2pack(v.x * scale, v.y * scale);
        *(uint32_t*)&Xh[r * 72 + d + 2] = h2pack(v.z * scale, v.w * scale);
    }
    __syncthreads();

    float acc[2][8][4] = {};
#pragma unroll
    for (int kc = 0; kc < 4; kc++) {
        const int k0 = kc * 16 + 2 * tg;
        uint32_t a[2][4];
#pragma unroll
        for (int mt = 0; mt < 2; mt++) {
            const int rr = wr + mt * 16 + gp;
            a[mt][0] = *(uint32_t*)&Xh[rr * 72 + k0];
            a[mt][1] = *(uint32_t*)&Xh[(rr + 8) * 72 + k0];
            a[mt][2] = *(uint32_t*)&Xh[rr * 72 + k0 + 8];
            a[mt][3] = *(uint32_t*)&Xh[(rr + 8) * 72 + k0 + 8];
        }
#pragma unroll
        for (int nt = 0; nt < 8; nt++) {
            const uint32_t b0 = *(uint32_t*)&Wh[(nt * 8 + gp) * 72 + k0];
            const uint32_t b1 = *(uint32_t*)&Wh[(nt * 8 + gp) * 72 + k0 + 8];
            mma_f16(acc[0][nt], a[0], b0, b1);
            mma_f16(acc[1][nt], a[1], b0, b1);
        }
    }
    __syncthreads();   // Xh free for epilogue reuse

    if (t != 0) {
        // q/k: smem-transpose to [r][c], then fully linear 16B writes
        __half* out = (t == 1) ? g_k : g_q;
#pragma unroll
        for (int mt = 0; mt < 2; mt++) {
            const int rr = wr + mt * 16 + gp;
#pragma unroll
            for (int nt = 0; nt < 8; nt++) {
                const int c = nt * 8 + 2 * tg;
                *(uint32_t*)&Xh[rr * 72 + c]       = h2pack(acc[mt][nt][0], acc[mt][nt][1]);
                *(uint32_t*)&Xh[(rr + 8) * 72 + c] = h2pack(acc[mt][nt][2], acc[mt][nt][3]);
            }
        }
        __syncthreads();
        for (int i = tid; i < 1024; i += 128) {
            int r = i >> 3, c8 = (i & 7) * 8;
            *(uint4*)&out[(size_t)(g0 + r) * 64 + c8] = *(uint4*)&Xh[r * 72 + c8];
        }
    } else {
        // v: transpose to (h,d,s-local) in smem, then 16B chunks to (n,h,d,s)
        __half* vsm = Xh;   // 16 * 64 * 8 = 8192 halves
#pragma unroll
        for (int mt = 0; mt < 2; mt++) {
#pragma unroll
            for (int nt = 0; nt < 8; nt++) {
                const int c = nt * 8 + 2 * tg;
                const int r0r = wr + mt * 16 + gp;
                const int r1r = r0r + 8;
                vsm[((r0r & 15) * 64 + c)     * 8 + (r0r >> 4)] = __float2half_rn(acc[mt][nt][0]);
                vsm[((r0r & 15) * 64 + c + 1) * 8 + (r0r >> 4)] = __float2half_rn(acc[mt][nt][1]);
                vsm[((r1r & 15) * 64 + c)     * 8 + (r1r >> 4)] = __float2half_rn(acc[mt][nt][2]);
                vsm[((r1r & 15) * 64 + c + 1) * 8 + (r1r >> 4)] = __float2half_rn(acc[mt][nt][3]);
            }
        }
        __syncthreads();
        const int n = g0 >> 15;
        const int s0 = (g0 >> 4) & (SEQ - 1);
        for (int i = tid; i < 1024; i += 128) {
            int h = i >> 6, d = i & 63;
            *(uint4*)&g_v[(size_t)((n * 16 + h) * 64 + d) * SEQ + s0] =
                *(uint4*)&vsm[(h * 64 + d) * 8];
        }
    }
}

// ---------------------------------------------------------------------------
// Kernel 2: flash attention on fp16 HMMA. R10 shape (128 thr, 4 warps x 32
// q-rows, 2 blocks/SM) + two softmax upgrades:
//  (a) exp via ex2.approx.f16x2 on packed (s*log2e + bias) — half the MUFU ops
//  (b) row sums via P_frag @ ones MMA into a dedicated accumulator — kills
//      128 FADDs/thread/tile and the tg shuffles; k-reduction spans tg lanes.
// Mask bias = -1e4 (f16 ex2 -> exact 0).
// ---------------------------------------------------------------------------
__global__ void __launch_bounds__(128, 2) flash_mma(const float* __restrict__ mask)
{
    __shared__ __align__(16) __half Kh[2 * 64 * 72];   // K bufs; Q staged here first
    __shared__ __align__(16) __half Vh[2 * 64 * 72];   // Vt bufs [d][s]
    __shared__ float msf[SEQ];                          // mask bias (log2-domain)

    const int tid = threadIdx.x;
    const int wid = tid >> 5, lane = tid & 31;
    const int gp = lane >> 2, tg = lane & 3;
    const int bh = blockIdx.y;
    const int n = bh >> 4, h = bh & 15;
    const int q0 = blockIdx.x * 128;
    const size_t base0 = ((size_t)n << 21) | (size_t)(h << 6);   // +s*1024+d
    const size_t vbase = (size_t)(n * 16 + h) * 64 * SEQ;        // +d*2048+s
    const float L2E = 1.4426950408889634f;

    // stage Q (fills both K bufs: 128*72 halves)
    for (int i = tid; i < 1024; i += 128) {
        int r = i >> 3, c8 = (i & 7) * 8;
        cp16(smem_u32(&Kh[r * 72 + c8]), g_q + base0 + (size_t)(q0 + r) * 1024 + c8);
    }
    CP_COMMIT();
    for (int i = tid; i < SEQ; i += 128)
        msf[i] = (mask[n * SEQ + i] == 0.0f) ? -1.0e4f : 0.0f;
    CP_WAIT0();
    __syncthreads();

    // Q fragments (m16n8k16 A): 4 k-chunks x 2 mt x 4 regs
    uint32_t qf[4][2][4];
#pragma unroll
    for (int kc = 0; kc < 4; kc++) {
        const int k0 = kc * 16 + 2 * tg;
#pragma unroll
        for (int mt = 0; mt < 2; mt++) {
            const int rr = wid * 32 + mt * 16 + gp;
            qf[kc][mt][0] = *(uint32_t*)&Kh[rr * 72 + k0];
            qf[kc][mt][1] = *(uint32_t*)&Kh[(rr + 8) * 72 + k0];
            qf[kc][mt][2] = *(uint32_t*)&Kh[rr * 72 + k0 + 8];
            qf[kc][mt][3] = *(uint32_t*)&Kh[(rr + 8) * 72 + k0 + 8];
        }
    }
    __syncthreads();

    // prefetch tile 0
    for (int i = tid; i < 1024; i += 128) {
        if (i < 512) {
            int r = i >> 3, c8 = (i & 7) * 8;
            cp16(smem_u32(&Kh[r * 72 + c8]), g_k + base0 + (size_t)r * 1024 + c8);
        } else {
            int d = (i - 512) >> 3, s8 = ((i - 512) & 7) * 8;
            cp16(smem_u32(&Vh[d * 72 + s8]), g_v + vbase + (size_t)d * SEQ + s8);
        }
    }
    CP_COMMIT();

    float ofrag[2][8][4] = {};
    float lacc[2][4] = {};        // row-sum accumulators (P @ ones)

    for (int kt = 0; kt < 32; kt++) {
        if (kt + 1 < 32) {
            const int buf = (kt + 1) & 1;
            for (int i = tid; i < 1024; i += 128) {
                if (i < 512) {
                    int r = i >> 3, c8 = (i & 7) * 8;
                    cp16(smem_u32(&Kh[buf * 4608 + r * 72 + c8]),
                         g_k + base0 + (size_t)((kt + 1) * 64 + r) * 1024 + c8);
                } else {
                    int d = (i - 512) >> 3, s8 = ((i - 512) & 7) * 8;
                    cp16(smem_u32(&Vh[buf * 4608 + d * 72 + s8]),
                         g_v + vbase + (size_t)d * SEQ + (kt + 1) * 64 + s8);
                }
            }
            CP_COMMIT();
            CP_WAIT1();
        } else {
            CP_WAIT0();
        }
        __syncthreads();

        const __half* Kb = Kh + (kt & 1) * 4608;
        const __half* Vb = Vh + (kt & 1) * 4608;

        // S = Q @ K^T  (32 x 64 per warp, 4 k-chunks of 16)
        float sf[2][8][4] = {};
#pragma unroll
        for (int kc = 0; kc < 4; kc++) {
            const int k0 = kc * 16 + 2 * tg;
#pragma unroll
            for (int nt = 0; nt < 8; nt++) {
                const uint32_t b0 = *(uint32_t*)&Kb[(nt * 8 + gp) * 72 + k0];
                const uint32_t b1 = *(uint32_t*)&Kb[(nt * 8 + gp) * 72 + k0 + 8];
                mma_f16(sf[0][nt], qf[kc][0], b0, b1);
                mma_f16(sf[1][nt], qf[kc][1], b0, b1);
            }
        }

        // softmax: t = s*log2e + bias (fp32 FFMA), pack f16x2, ex2.f16x2.
        // Packed results land directly in PV A-fragment slots.
        uint32_t pa[2][4][4];
#pragma unroll
        for (int mt = 0; mt < 2; mt++) {
#pragma unroll
            for (int nt = 0; nt < 8; nt++) {
                const int c0 = nt * 8 + 2 * tg;
                const float mb0 = msf[kt * 64 + c0];
                const float mb1 = msf[kt * 64 + c0 + 1];
                float t0 = fmaf(sf[mt][nt][0], L2E, mb0);
                float t1 = fmaf(sf[mt][nt][1], L2E, mb1);
                float t2 = fmaf(sf[mt][nt][2], L2E, mb0);
                float t3 = fmaf(sf[mt][nt][3], L2E, mb1);
                const int j = nt >> 1;
                if ((nt & 1) == 0) {
                    pa[mt][j][0] = ex2h2(h2pack(t0, t1));
                    pa[mt][j][1] = ex2h2(h2pack(t2, t3));
                } else {
                    pa[mt][j][2] = ex2h2(h2pack(t0, t1));
                    pa[mt][j][3] = ex2h2(h2pack(t2, t3));
                }
            }
        }

        // O += P @ V ; row sums += P @ ones (extra MMA per j per mt)
#pragma unroll
        for (int j = 0; j < 4; j++) {
            const int k0 = j * 16 + 2 * tg;
#pragma unroll
            for (int nt = 0; nt < 8; nt++) {
                const uint32_t b0 = *(uint32_t*)&Vb[(nt * 8 + gp) * 72 + k0];
                const uint32_t b1 = *(uint32_t*)&Vb[(nt * 8 + gp) * 72 + k0 + 8];
                mma_f16(ofrag[0][nt], pa[0][j], b0, b1);
                mma_f16(ofrag[1][nt], pa[1][j], b0, b1);
            }
            mma_f16(lacc[0], pa[0][j], HALF2_ONES, HALF2_ONES);
            mma_f16(lacc[1], pa[1][j], HALF2_ONES, HALF2_ONES);
        }
        __syncthreads();
    }

    // epilogue: normalize -> half, per-warp smem transpose, linear 16B stores
    // lacc[mt][0] = rowsum(row gp), lacc[mt][2] = rowsum(row gp+8): MMA's
    // k-reduction already summed across tg lanes — no shuffles needed.
    __half* aobuf = Kh + wid * 2304;   // 32 x 72 halves per warp
#pragma unroll
    for (int mt = 0; mt < 2; mt++) {
        const float inv0 = 1.0f / lacc[mt][0];
        const float inv1 = 1.0f / lacc[mt][2];
        const int rr = mt * 16 + gp;
#pragma unroll
        for (int nt = 0; nt < 8; nt++) {
            const int c = nt * 8 + 2 * tg;
            *(uint32_t*)&aobuf[rr * 72 + c] =
                h2pack(ofrag[mt][nt][0] * inv0, ofrag[mt][nt][1] * inv0);
            *(uint32_t*)&aobuf[(rr + 8) * 72 + c] =
                h2pack(ofrag[mt][nt][2] * inv1, ofrag[mt][nt][3] * inv1);
        }
    }
    __syncwarp();
    const size_t obase = (size_t)(n * SEQ + q0 + wid * 32) * 1024 + h * 64;
    for (int i = lane; i < 256; i += 32) {
        int r = i >> 3, c8 = (i & 7) * 8;
        *(uint4*)&g_ao[obase + (size_t)r * 1024 + c8] = *(uint4*)&aobuf[r * 72 + c8];
    }
}

// ---------------------------------------------------------------------------
// Kernel 3: out = g_ao @ Wo + bo on fp16 HMMA. 128 threads, 4 warps (2x2),
// warp tile 64x64, BK=32 (2 k-chunks of 16). cp.async double-buffered.
// ---------------------------------------------------------------------------
#define OG_SMEM 71680   // staging 40960B (half) + epilogue float reuse

__global__ void __launch_bounds__(128, 2) out_gemm(
    const float* __restrict__ bo, float* __restrict__ out)
{
    extern __shared__ __align__(16) char og[];
    __half* Ash = (__half*)og;            // [2][128][40]
    __half* Bsh = Ash + 10240;            // [2][128][40]

    const int tid = threadIdx.x;
    const int wid = tid >> 5, lane = tid & 31;
    const int gp = lane >> 2, tg = lane & 3;
    const int wr = (wid & 1) * 64;
    const int wc = (wid >> 1) * 64;
    const int j0 = blockIdx.x * 128;
    const int m0 = blockIdx.y * 128;

    float acc[4][8][4] = {};

    for (int i = tid; i < 1024; i += 128) {
        if (i < 512) {
            int r = i >> 2, c8 = (i & 3) * 8;
            cp16(smem_u32(&Ash[r * 40 + c8]), g_ao + (size_t)(m0 + r) * 1024 + c8);
        } else {
            int r = (i - 512) >> 2, c8 = ((i - 512) & 3) * 8;
            cp16(smem_u32(&Bsh[r * 40 + c8]), g_wo + (size_t)(j0 + r) * 1024 + c8);
        }
    }
    CP_COMMIT();

    for (int kt = 0; kt < 32; kt++) {
        if (kt + 1 < 32) {
            const int buf = (kt + 1) & 1;
            const int k0g = (kt + 1) * 32;
            for (int i = tid; i < 1024; i += 128) {
                if (i < 512) {
                    int r = i >> 2, c8 = (i & 3) * 8;
                    cp16(smem_u32(&Ash[buf * 5120 + r * 40 + c8]),
                         g_ao + (size_t)(m0 + r) * 1024 + k0g + c8);
                } else {
                    int r = (i - 512) >> 2, c8 = ((i - 512) & 3) * 8;
                    cp16(smem_u32(&Bsh[buf * 5120 + r * 40 + c8]),
                         g_wo + (size_t)(j0 + r) * 1024 + k0g + c8);
                }
            }
            CP_COMMIT();
            CP_WAIT1();
        } else {
            CP_WAIT0();
        }
        __syncthreads();

        const __half* Ab = Ash + (kt & 1) * 5120;
        const __half* Bb = Bsh + (kt & 1) * 5120;
#pragma unroll
        for (int kc = 0; kc < 2; kc++) {
            const int k0 = kc * 16 + 2 * tg;
            uint32_t a[4][4];
#pragma unroll
            for (int mt = 0; mt < 4; mt++) {
                const int rr = wr + mt * 16 + gp;
                a[mt][0] = *(uint32_t*)&Ab[rr * 40 + k0];
                a[mt][1] = *(uint32_t*)&Ab[(rr + 8) * 40 + k0];
                a[mt][2] = *(uint32_t*)&Ab[rr * 40 + k0 + 8];
                a[mt][3] = *(uint32_t*)&Ab[(rr + 8) * 40 + k0 + 8];
            }
#pragma unroll
            for (int nt = 0; nt < 8; nt++) {
                const uint32_t b0 = *(uint32_t*)&Bb[(wc + nt * 8 + gp) * 40 + k0];
                const uint32_t b1 = *(uint32_t*)&Bb[(wc + nt * 8 + gp) * 40 + k0 + 8];
                mma_f16(acc[0][nt], a[0], b0, b1);
                mma_f16(acc[1][nt], a[1], b0, b1);
                mma_f16(acc[2][nt], a[2], b0, b1);
                mma_f16(acc[3][nt], a[3], b0, b1);
            }
        }
        __syncthreads();
    }

    // epilogue: bias + smem-transpose per warp (64x68 f32), linear stores
    float* sf = (float*)og + wid * 4352;
#pragma unroll
    for (int mt = 0; mt < 4; mt++) {
        const int rr = mt * 16 + gp;
#pragma unroll
        for (int nt = 0; nt < 8; nt++) {
            const int cc = nt * 8 + 2 * tg;
            const float b0v = bo[j0 + wc + cc];
            const float b1v = bo[j0 + wc + cc + 1];
            sf[rr * 68 + cc]           = acc[mt][nt][0] + b0v;
            sf[rr * 68 + cc + 1]       = acc[mt][nt][1] + b1v;
            sf[(rr + 8) * 68 + cc]     = acc[mt][nt][2] + b0v;
            sf[(rr + 8) * 68 + cc + 1] = acc[mt][nt][3] + b1v;
        }
    }
    __syncwarp();
    const size_t obase = (size_t)(m0 + wr) * 1024 + j0 + wc;
    for (int i = lane; i < 1024; i += 32) {
        int r = i >> 4, c4 = (i & 15) * 4;
        *(float4*)&out[obase + (size_t)r * 1024 + c4] = *(float4*)&sf[r * 68 + c4];
    }
}

// ---------------------------------------------------------------------------
extern "C" void kernel_launch(void* const* d_in, const int* in_sizes, int n_in,
                              void* d_out, int out_size)
{
    const float* values = (const float*)d_in[0];
    const float* keys   = (const float*)d_in[1];
    const float* query  = (const float*)d_in[2];
    const float* mask   = (const float*)d_in[3];
    const float* Wv     = (const float*)d_in[4];
    const float* Wk     = (const float*)d_in[5];
    const float* Wq     = (const float*)d_in[6];
    const float* Wo     = (const float*)d_in[7];
    const float* bo     = (const float*)d_in[8];
    float* out = (float*)d_out;

    cudaFuncSetAttribute(out_gemm, cudaFuncAttributeMaxDynamicSharedMemorySize, OG_SMEM);

    proj_mma<<<dim3(ROWS_TOT / 128, 3), 128>>>(values, keys, query, Wv, Wk, Wq);
    wo_cvt<<<dim3(32, 32), 256>>>(Wo);
    flash_mma<<<dim3(SEQ / 128, NH), 128>>>(mask);
    out_gemm<<<dim3(EMB / 128, (NB * SEQ) / 128), 128, OG_SMEM>>>(bo, out);
}

// round 13
// speedup vs baseline: 1.3290x; 1.1194x over previous
#include <cuda_runtime.h>
#include <cuda_fp16.h>
#include <cstdint>

// Fixed problem shape
#define NB   4
#define SEQ  2048
#define EMB  1024
#define HEADS 16
#define DH   64
#define NH   (NB * HEADS)
#define ROWS_TOT (NB * SEQ * HEADS)   // 131072

// Scratch (device globals), all fp16.
// g_q/g_k: (n,s,h,d). g_v: (n,h,d,s). g_ao: (n,q,h,d). g_wo: Wo transposed [j][k].
__device__ __half g_q[ROWS_TOT * DH];
__device__ __half g_k[ROWS_TOT * DH];
__device__ __half g_v[ROWS_TOT * DH];
__device__ __half g_ao[NB * SEQ * EMB];
__device__ __half g_wo[EMB * EMB];

#define HALF2_ONES 0x3C003C00u   // (1.0h, 1.0h)

// ===========================================================================
// helpers
// ===========================================================================
__device__ __forceinline__ uint32_t h2pack(float lo, float hi) {
    uint32_t r;
    asm("cvt.rn.f16x2.f32 %0, %1, %2;" : "=r"(r) : "f"(hi), "f"(lo));
    return r;
}
__device__ __forceinline__ uint32_t ex2h2(uint32_t x) {
    uint32_t r;
    asm("ex2.approx.f16x2 %0, %1;" : "=r"(r) : "r"(x));
    return r;
}
__device__ __forceinline__ void mma_f16(float* d, const uint32_t* a,
                                        uint32_t b0, uint32_t b1) {
    asm volatile(
        "mma.sync.aligned.m16n8k16.row.col.f32.f16.f16.f32 "
        "{%0,%1,%2,%3}, {%4,%5,%6,%7}, {%8,%9}, {%0,%1,%2,%3};"
        : "+f"(d[0]), "+f"(d[1]), "+f"(d[2]), "+f"(d[3])
        : "r"(a[0]), "r"(a[1]), "r"(a[2]), "r"(a[3]), "r"(b0), "r"(b1));
}
__device__ __forceinline__ void ldm_x4(uint32_t& r0, uint32_t& r1,
                                       uint32_t& r2, uint32_t& r3, uint32_t addr) {
    asm volatile("ldmatrix.sync.aligned.m8n8.x4.shared.b16 {%0,%1,%2,%3}, [%4];"
                 : "=r"(r0), "=r"(r1), "=r"(r2), "=r"(r3) : "r"(addr));
}
__device__ __forceinline__ uint32_t smem_u32(const void* p) {
    uint32_t a;
    asm("{ .reg .u64 t; cvta.to.shared.u64 t, %1; cvt.u32.u64 %0, t; }"
        : "=r"(a) : "l"(p));
    return a;
}
__device__ __forceinline__ void cp16(uint32_t dst, const void* src) {
    asm volatile("cp.async.cg.shared.global [%0], [%1], 16;"
                 :: "r"(dst), "l"(src) : "memory");
}
#define CP_COMMIT() asm volatile("cp.async.commit_group;" ::: "memory")
#define CP_WAIT0()  asm volatile("cp.async.wait_group 0;" ::: "memory")
#define CP_WAIT1()  asm volatile("cp.async.wait_group 1;" ::: "memory")

// ---------------------------------------------------------------------------
// Kernel 1: per-head projections on HMMA fp16 (grid.y 0..2) + Wo transpose
// (grid.y == 3). Outputs: q/k (n,s,h,d); v (n,h,d,s); g_wo [j][k].
// ---------------------------------------------------------------------------
__global__ void __launch_bounds__(128) proj_mma(
    const float* __restrict__ vals, const float* __restrict__ keys,
    const float* __restrict__ qry,
    const float* __restrict__ Wv, const float* __restrict__ Wk,
    const float* __restrict__ Wq, const float* __restrict__ Wo)
{
    __shared__ __align__(16) __half Xh[128 * 72];   // X tile [r][d]
    __shared__ __align__(16) __half Wh[64 * 72];    // W transposed [c][d]

    const int t = blockIdx.y;
    const int tid = threadIdx.x;

    if (t == 3) {   // Wo transpose slice: one 32x32 tile per block
        float* tf = (float*)Xh;     // 32 x 33 floats
        const int b = blockIdx.x;
        const int j0 = (b & 31) * 32, k0 = (b >> 5) * 32;
        const int tx = tid & 31, ty = tid >> 5;   // ty 0..3
#pragma unroll
        for (int i = 0; i < 8; i++)
            tf[(ty + 4 * i) * 33 + tx] = Wo[(size_t)(k0 + ty + 4 * i) * EMB + j0 + tx];
        __syncthreads();
#pragma unroll
        for (int i = 0; i < 8; i++)
            g_wo[(size_t)(j0 + ty + 4 * i) * EMB + k0 + tx] =
                __float2half_rn(tf[tx * 33 + ty + 4 * i]);
        return;
    }

    const float* X = (t == 0) ? vals : (t == 1) ? keys : qry;
    const float* W = (t == 0) ? Wv   : (t == 1) ? Wk   : Wq;
    const float scale = (t == 2) ? 0.03125f : 1.0f;

    const int wid = tid >> 5, lane = tid & 31;
    const int gp = lane >> 2, tg = lane & 3;
    const int g0 = blockIdx.x * 128;
    const int wr = wid * 32;

    for (int i = tid; i < 4096; i += 128) {
        int d = i >> 6, c = i & 63;
        Wh[c * 72 + d] = __float2half_rn(W[i]);
    }
    for (int idx = tid * 4; idx < 128 * 64; idx += 512) {
        int r = idx >> 6, d = idx & 63;
        float4 v = *(const float4*)&X[(g0 + r) * 64 + d];
        *(uint32_t*)&Xh[r * 72 + d]     = h2pack(v.x * scale, v.y * scale);
        *(uint32_t*)&Xh[r * 72 + d + 2] = h2pack(v.z * scale, v.w * scale);
    }
    __syncthreads();

    float acc[2][8][4] = {};
#pragma unroll
    for (int kc = 0; kc < 4; kc++) {
        const int k0 = kc * 16 + 2 * tg;
        uint32_t a[2][4];
#pragma unroll
        for (int mt = 0; mt < 2; mt++) {
            const int rr = wr + mt * 16 + gp;
            a[mt][0] = *(uint32_t*)&Xh[rr * 72 + k0];
            a[mt][1] = *(uint32_t*)&Xh[(rr + 8) * 72 + k0];
            a[mt][2] = *(uint32_t*)&Xh[rr * 72 + k0 + 8];
            a[mt][3] = *(uint32_t*)&Xh[(rr + 8) * 72 + k0 + 8];
        }
#pragma unroll
        for (int nt = 0; nt < 8; nt++) {
            const uint32_t b0 = *(uint32_t*)&Wh[(nt * 8 + gp) * 72 + k0];
            const uint32_t b1 = *(uint32_t*)&Wh[(nt * 8 + gp) * 72 + k0 + 8];
            mma_f16(acc[0][nt], a[0], b0, b1);
            mma_f16(acc[1][nt], a[1], b0, b1);
        }
    }
    __syncthreads();   // Xh free for epilogue reuse

    if (t != 0) {
        __half* out = (t == 1) ? g_k : g_q;
#pragma unroll
        for (int mt = 0; mt < 2; mt++) {
            const int rr = wr + mt * 16 + gp;
#pragma unroll
            for (int nt = 0; nt < 8; nt++) {
                const int c = nt * 8 + 2 * tg;
                *(uint32_t*)&Xh[rr * 72 + c]       = h2pack(acc[mt][nt][0], acc[mt][nt][1]);
                *(uint32_t*)&Xh[(rr + 8) * 72 + c] = h2pack(acc[mt][nt][2], acc[mt][nt][3]);
            }
        }
        __syncthreads();
        for (int i = tid; i < 1024; i += 128) {
            int r = i >> 3, c8 = (i & 7) * 8;
            *(uint4*)&out[(size_t)(g0 + r) * 64 + c8] = *(uint4*)&Xh[r * 72 + c8];
        }
    } else {
        __half* vsm = Xh;   // (h, d, s-local): 16*64*8 halves
#pragma unroll
        for (int mt = 0; mt < 2; mt++) {
#pragma unroll
            for (int nt = 0; nt < 8; nt++) {
                const int c = nt * 8 + 2 * tg;
                const int r0r = wr + mt * 16 + gp;
                const int r1r = r0r + 8;
                vsm[((r0r & 15) * 64 + c)     * 8 + (r0r >> 4)] = __float2half_rn(acc[mt][nt][0]);
                vsm[((r0r & 15) * 64 + c + 1) * 8 + (r0r >> 4)] = __float2half_rn(acc[mt][nt][1]);
                vsm[((r1r & 15) * 64 + c)     * 8 + (r1r >> 4)] = __float2half_rn(acc[mt][nt][2]);
                vsm[((r1r & 15) * 64 + c + 1) * 8 + (r1r >> 4)] = __float2half_rn(acc[mt][nt][3]);
            }
        }
        __syncthreads();
        const int n = g0 >> 15;
        const int s0 = (g0 >> 4) & (SEQ - 1);
        for (int i = tid; i < 1024; i += 128) {
            int h = i >> 6, d = i & 63;
            *(uint4*)&g_v[(size_t)((n * 16 + h) * 64 + d) * SEQ + s0] =
                *(uint4*)&vsm[(h * 64 + d) * 8];
        }
    }
}

// ---------------------------------------------------------------------------
// Kernel 2: flash attention, fp16 HMMA. 128 thr, 4 warps x 32 q-rows,
// 3 blocks/SM (mt-split halves live sf/pa regs). B-fragments via
// ldmatrix.x4 (4x fewer LSU issues). ex2.f16x2 softmax, MMA row-sums.
// ---------------------------------------------------------------------------
__global__ void __launch_bounds__(128, 3) flash_mma(const float* __restrict__ mask)
{
    __shared__ __align__(16) __half Kh[2 * 64 * 72];   // K bufs; Q staged here first
    __shared__ __align__(16) __half Vh[2 * 64 * 72];   // Vt bufs [d][s]
    __shared__ float msf[SEQ];                          // mask bias (log2-domain)

    const int tid = threadIdx.x;
    const int wid = tid >> 5, lane = tid & 31;
    const int gp = lane >> 2, tg = lane & 3;
    const int bh = blockIdx.y;
    const int n = bh >> 4, h = bh & 15;
    const int q0 = blockIdx.x * 128;
    const size_t base0 = ((size_t)n << 21) | (size_t)(h << 6);   // +s*1024+d
    const size_t vbase = (size_t)(n * 16 + h) * 64 * SEQ;        // +d*2048+s
    const float L2E = 1.4426950408889634f;

    const uint32_t sbK = smem_u32(Kh);
    const uint32_t sbV = smem_u32(Vh);
    // ldmatrix lane offset (bytes) for the n-major B tiles (stride 72 halves):
    // lanes 0-7: b0 rows of nt=2m; 8-15: b1 (col+8); 16-23: b0 of nt=2m+1; 24-31: b1.
    const uint32_t lmB2 = (((lane & 7) + ((lane & 16) >> 1)) * 72 + (lane & 8)) * 2;

    // stage Q (fills both K bufs: 128*72 halves)
    for (int i = tid; i < 1024; i += 128) {
        int r = i >> 3, c8 = (i & 7) * 8;
        cp16(sbK + (uint32_t)(r * 72 + c8) * 2u, g_q + base0 + (size_t)(q0 + r) * 1024 + c8);
    }
    CP_COMMIT();
    for (int i = tid; i < SEQ; i += 128)
        msf[i] = (mask[n * SEQ + i] == 0.0f) ? -1.0e4f : 0.0f;
    CP_WAIT0();
    __syncthreads();

    // Q fragments (m16n8k16 A): 4 k-chunks x 2 mt x 4 regs
    uint32_t qf[4][2][4];
#pragma unroll
    for (int kc = 0; kc < 4; kc++) {
        const int k0 = kc * 16 + 2 * tg;
#pragma unroll
        for (int mt = 0; mt < 2; mt++) {
            const int rr = wid * 32 + mt * 16 + gp;
            qf[kc][mt][0] = *(uint32_t*)&Kh[rr * 72 + k0];
            qf[kc][mt][1] = *(uint32_t*)&Kh[(rr + 8) * 72 + k0];
            qf[kc][mt][2] = *(uint32_t*)&Kh[rr * 72 + k0 + 8];
            qf[kc][mt][3] = *(uint32_t*)&Kh[(rr + 8) * 72 + k0 + 8];
        }
    }
    __syncthreads();

    // prefetch tile 0
    for (int i = tid; i < 1024; i += 128) {
        if (i < 512) {
            int r = i >> 3, c8 = (i & 7) * 8;
            cp16(sbK + (uint32_t)(r * 72 + c8) * 2u, g_k + base0 + (size_t)r * 1024 + c8);
        } else {
            int d = (i - 512) >> 3, s8 = ((i - 512) & 7) * 8;
            cp16(sbV + (uint32_t)(d * 72 + s8) * 2u, g_v + vbase + (size_t)d * SEQ + s8);
        }
    }
    CP_COMMIT();

    float ofrag[2][8][4] = {};
    float lacc[2][4] = {};        // row-sum accumulators (P @ ones)

    for (int kt = 0; kt < 32; kt++) {
        if (kt + 1 < 32) {
            const int buf = (kt + 1) & 1;
            for (int i = tid; i < 1024; i += 128) {
                if (i < 512) {
                    int r = i >> 3, c8 = (i & 7) * 8;
                    cp16(sbK + (uint32_t)(buf * 4608 + r * 72 + c8) * 2u,
                         g_k + base0 + (size_t)((kt + 1) * 64 + r) * 1024 + c8);
                } else {
                    int d = (i - 512) >> 3, s8 = ((i - 512) & 7) * 8;
                    cp16(sbV + (uint32_t)(buf * 4608 + d * 72 + s8) * 2u,
                         g_v + vbase + (size_t)d * SEQ + (kt + 1) * 64 + s8);
                }
            }
            CP_COMMIT();
            CP_WAIT1();
        } else {
            CP_WAIT0();
        }
        __syncthreads();

        const uint32_t kb = sbK + (kt & 1) * 9216 + lmB2;
        const uint32_t vb = sbV + (kt & 1) * 9216 + lmB2;

#pragma unroll
        for (int mt = 0; mt < 2; mt++) {
            // S = Q @ K^T  (16 x 64 per mt)
            float sfr[8][4] = {};
#pragma unroll
            for (int kc = 0; kc < 4; kc++) {
#pragma unroll
                for (int m = 0; m < 4; m++) {
                    uint32_t b0, b1, b2, b3;
                    ldm_x4(b0, b1, b2, b3, kb + m * 2304 + kc * 32);
                    mma_f16(sfr[2 * m],     qf[kc][mt], b0, b1);
                    mma_f16(sfr[2 * m + 1], qf[kc][mt], b2, b3);
                }
            }

            // softmax: t = s*log2e + bias; ex2.f16x2 -> PV A-fragments
            uint32_t pa[4][4];
#pragma unroll
            for (int nt = 0; nt < 8; nt++) {
                const int c0 = nt * 8 + 2 * tg;
                const float mb0 = msf[kt * 64 + c0];
                const float mb1 = msf[kt * 64 + c0 + 1];
                float t0 = fmaf(sfr[nt][0], L2E, mb0);
                float t1 = fmaf(sfr[nt][1], L2E, mb1);
                float t2 = fmaf(sfr[nt][2], L2E, mb0);
                float t3 = fmaf(sfr[nt][3], L2E, mb1);
                const int j = nt >> 1;
                if ((nt & 1) == 0) {
                    pa[j][0] = ex2h2(h2pack(t0, t1));
                    pa[j][1] = ex2h2(h2pack(t2, t3));
                } else {
                    pa[j][2] = ex2h2(h2pack(t0, t1));
                    pa[j][3] = ex2h2(h2pack(t2, t3));
                }
            }

            // O += P @ V ; row sums += P @ ones
#pragma unroll
            for (int j = 0; j < 4; j++) {
#pragma unroll
                for (int m = 0; m < 4; m++) {
                    uint32_t b0, b1, b2, b3;
                    ldm_x4(b0, b1, b2, b3, vb + m * 2304 + j * 32);
                    mma_f16(ofrag[mt][2 * m],     pa[j], b0, b1);
                    mma_f16(ofrag[mt][2 * m + 1], pa[j], b2, b3);
                }
                mma_f16(lacc[mt], pa[j], HALF2_ONES, HALF2_ONES);
            }
        }
        __syncthreads();   // all warps done with this K/V buffer
    }

    // epilogue: normalize -> half, per-warp smem transpose, linear 16B stores
    // lacc[mt][0] = rowsum(gp), lacc[mt][2] = rowsum(gp+8) (k-reduce spans tg)
    __half* aobuf = Kh + wid * 2304;   // 32 x 72 halves per warp
#pragma unroll
    for (int mt = 0; mt < 2; mt++) {
        const float inv0 = 1.0f / lacc[mt][0];
        const float inv1 = 1.0f / lacc[mt][2];
        const int rr = mt * 16 + gp;
#pragma unroll
        for (int nt = 0; nt < 8; nt++) {
            const int c = nt * 8 + 2 * tg;
            *(uint32_t*)&aobuf[rr * 72 + c] =
                h2pack(ofrag[mt][nt][0] * inv0, ofrag[mt][nt][1] * inv0);
            *(uint32_t*)&aobuf[(rr + 8) * 72 + c] =
                h2pack(ofrag[mt][nt][2] * inv1, ofrag[mt][nt][3] * inv1);
        }
    }
    __syncwarp();
    const size_t obase = (size_t)(n * SEQ + q0 + wid * 32) * 1024 + h * 64;
    for (int i = lane; i < 256; i += 32) {
        int r = i >> 3, c8 = (i & 7) * 8;
        *(uint4*)&g_ao[obase + (size_t)r * 1024 + c8] = *(uint4*)&aobuf[r * 72 + c8];
    }
}

// ---------------------------------------------------------------------------
// Kernel 3: out = g_ao @ Wo + bo on fp16 HMMA. 128 thr, 4 warps (2x2),
// warp tile 64x64, BK=32. ldmatrix.x4 for A and B fragments.
// ---------------------------------------------------------------------------
#define OG_SMEM 71680

__global__ void __launch_bounds__(128, 2) out_gemm(
    const float* __restrict__ bo, float* __restrict__ out)
{
    extern __shared__ __align__(16) char og[];
    __half* Ash = (__half*)og;            // [2][128][40]
    __half* Bsh = Ash + 10240;            // [2][128][40]

    const int tid = threadIdx.x;
    const int wid = tid >> 5, lane = tid & 31;
    const int gp = lane >> 2, tg = lane & 3;
    const int wr = (wid & 1) * 64;
    const int wc = (wid >> 1) * 64;
    const int j0 = blockIdx.x * 128;
    const int m0 = blockIdx.y * 128;

    const uint32_t sbA = smem_u32(Ash);
    const uint32_t sbB = smem_u32(Bsh);
    // A (m-major, stride 40): matrices {M(rr,k0),M(rr+8,k0),M(rr,k0+8),M(rr+8,k0+8)}
    const uint32_t lmA2 = ((lane & 15) * 40 + ((lane & 16) >> 1)) * 2;
    // B (n-major, stride 40): same scheme as flash
    const uint32_t lmB2 = (((lane & 7) + ((lane & 16) >> 1)) * 40 + (lane & 8)) * 2;

    float acc[4][8][4] = {};

    for (int i = tid; i < 1024; i += 128) {
        if (i < 512) {
            int r = i >> 2, c8 = (i & 3) * 8;
            cp16(sbA + (uint32_t)(r * 40 + c8) * 2u, g_ao + (size_t)(m0 + r) * 1024 + c8);
        } else {
            int r = (i - 512) >> 2, c8 = ((i - 512) & 3) * 8;
            cp16(sbB + (uint32_t)(r * 40 + c8) * 2u, g_wo + (size_t)(j0 + r) * 1024 + c8);
        }
    }
    CP_COMMIT();

    for (int kt = 0; kt < 32; kt++) {
        if (kt + 1 < 32) {
            const int buf = (kt + 1) & 1;
            const int k0g = (kt + 1) * 32;
            for (int i = tid; i < 1024; i += 128) {
                if (i < 512) {
                    int r = i >> 2, c8 = (i & 3) * 8;
                    cp16(sbA + (uint32_t)(buf * 5120 + r * 40 + c8) * 2u,
                         g_ao + (size_t)(m0 + r) * 1024 + k0g + c8);
                } else {
                    int r = (i - 512) >> 2, c8 = ((i - 512) & 3) * 8;
                    cp16(sbB + (uint32_t)(buf * 5120 + r * 40 + c8) * 2u,
                         g_wo + (size_t)(j0 + r) * 1024 + k0g + c8);
                }
            }
            CP_COMMIT();
            CP_WAIT1();
        } else {
            CP_WAIT0();
        }
        __syncthreads();

        const uint32_t abase = sbA + (kt & 1) * 10240 + (uint32_t)(wr * 40) * 2 + lmA2;
        const uint32_t bbase = sbB + (kt & 1) * 10240 + (uint32_t)(wc * 40) * 2 + lmB2;
#pragma unroll
        for (int kc = 0; kc < 2; kc++) {
            uint32_t a[4][4];
#pragma unroll
            for (int mt = 0; mt < 4; mt++)
                ldm_x4(a[mt][0], a[mt][1], a[mt][2], a[mt][3],
                       abase + mt * 1280 + kc * 32);
#pragma unroll
            for (int m = 0; m < 4; m++) {
                uint32_t b0, b1, b2, b3;
                ldm_x4(b0, b1, b2, b3, bbase + m * 1280 + kc * 32);
#pragma unroll
                for (int mt = 0; mt < 4; mt++) {
                    mma_f16(acc[mt][2 * m],     a[mt], b0, b1);
                    mma_f16(acc[mt][2 * m + 1], a[mt], b2, b3);
                }
            }
        }
        __syncthreads();
    }

    // epilogue: bias + smem-transpose per warp (64x68 f32), linear stores
    float* sf = (float*)og + wid * 4352;
#pragma unroll
    for (int mt = 0; mt < 4; mt++) {
        const int rr = mt * 16 + gp;
#pragma unroll
        for (int nt = 0; nt < 8; nt++) {
            const int cc = nt * 8 + 2 * tg;
            const float b0v = bo[j0 + wc + cc];
            const float b1v = bo[j0 + wc + cc + 1];
            sf[rr * 68 + cc]           = acc[mt][nt][0] + b0v;
            sf[rr * 68 + cc + 1]       = acc[mt][nt][1] + b1v;
            sf[(rr + 8) * 68 + cc]     = acc[mt][nt][2] + b0v;
            sf[(rr + 8) * 68 + cc + 1] = acc[mt][nt][3] + b1v;
        }
    }
    __syncwarp();
    const size_t obase = (size_t)(m0 + wr) * 1024 + j0 + wc;
    for (int i = lane; i < 1024; i += 32) {
        int r = i >> 4, c4 = (i & 15) * 4;
        *(float4*)&out[obase + (size_t)r * 1024 + c4] = *(float4*)&sf[r * 68 + c4];
    }
}

// ---------------------------------------------------------------------------
extern "C" void kernel_launch(void* const* d_in, const int* in_sizes, int n_in,
                              void* d_out, int out_size)
{
    const float* values = (const float*)d_in[0];
    const float* keys   = (const float*)d_in[1];
    const float* query  = (const float*)d_in[2];
    const float* mask   = (const float*)d_in[3];
    const float* Wv     = (const float*)d_in[4];
    const float* Wk     = (const float*)d_in[5];
    const float* Wq     = (const float*)d_in[6];
    const float* Wo     = (const float*)d_in[7];
    const float* bo     = (const float*)d_in[8];
    float* out = (float*)d_out;

    cudaFuncSetAttribute(out_gemm, cudaFuncAttributeMaxDynamicSharedMemorySize, OG_SMEM);

    // y=0..2: V/K/Q projections; y=3: Wo transpose (1024 tiles of 32x32)
    proj_mma<<<dim3(ROWS_TOT / 128, 4), 128>>>(values, keys, query, Wv, Wk, Wq, Wo);
    flash_mma<<<dim3(SEQ / 128, NH), 128>>>(mask);
    out_gemm<<<dim3(EMB / 128, (NB * SEQ) / 128), 128, OG_SMEM>>>(bo, out);
}

// round 14
// speedup vs baseline: 1.3297x; 1.0005x over previous
#include <cuda_runtime.h>
#include <cuda_fp16.h>
#include <cstdint>

// Fixed problem shape
#define NB   4
#define SEQ  2048
#define EMB  1024
#define HEADS 16
#define DH   64
#define NH   (NB * HEADS)
#define ROWS_TOT (NB * SEQ * HEADS)   // 131072

// Scratch (device globals), all fp16.
// g_q/g_k: (n,s,h,d). g_v: (n,h,d,s). g_ao: (n,q,h,d). g_wo: Wo transposed [j][k].
__device__ __half g_q[ROWS_TOT * DH];
__device__ __half g_k[ROWS_TOT * DH];
__device__ __half g_v[ROWS_TOT * DH];
__device__ __half g_ao[NB * SEQ * EMB];
__device__ __half g_wo[EMB * EMB];

#define HALF2_ONES 0x3C003C00u   // (1.0h, 1.0h)

// ===========================================================================
// helpers
// ===========================================================================
__device__ __forceinline__ uint32_t h2pack(float lo, float hi) {
    uint32_t r;
    asm("cvt.rn.f16x2.f32 %0, %1, %2;" : "=r"(r) : "f"(hi), "f"(lo));
    return r;
}
__device__ __forceinline__ uint32_t ex2h2(uint32_t x) {
    uint32_t r;
    asm("ex2.approx.f16x2 %0, %1;" : "=r"(r) : "r"(x));
    return r;
}
__device__ __forceinline__ void mma_f16(float* d, const uint32_t* a,
                                        uint32_t b0, uint32_t b1) {
    asm volatile(
        "mma.sync.aligned.m16n8k16.row.col.f32.f16.f16.f32 "
        "{%0,%1,%2,%3}, {%4,%5,%6,%7}, {%8,%9}, {%0,%1,%2,%3};"
        : "+f"(d[0]), "+f"(d[1]), "+f"(d[2]), "+f"(d[3])
        : "r"(a[0]), "r"(a[1]), "r"(a[2]), "r"(a[3]), "r"(b0), "r"(b1));
}
__device__ __forceinline__ void ldm_x4(uint32_t& r0, uint32_t& r1,
                                       uint32_t& r2, uint32_t& r3, uint32_t addr) {
    asm volatile("ldmatrix.sync.aligned.m8n8.x4.shared.b16 {%0,%1,%2,%3}, [%4];"
                 : "=r"(r0), "=r"(r1), "=r"(r2), "=r"(r3) : "r"(addr));
}
__device__ __forceinline__ uint32_t smem_u32(const void* p) {
    uint32_t a;
    asm("{ .reg .u64 t; cvta.to.shared.u64 t, %1; cvt.u32.u64 %0, t; }"
        : "=r"(a) : "l"(p));
    return a;
}
__device__ __forceinline__ void cp16(uint32_t dst, const void* src) {
    asm volatile("cp.async.cg.shared.global [%0], [%1], 16;"
                 :: "r"(dst), "l"(src) : "memory");
}
#define CP_COMMIT() asm volatile("cp.async.commit_group;" ::: "memory")
#define CP_WAIT0()  asm volatile("cp.async.wait_group 0;" ::: "memory")
#define CP_WAIT1()  asm volatile("cp.async.wait_group 1;" ::: "memory")

// ---------------------------------------------------------------------------
// Kernel 1: per-head projections on HMMA fp16 (grid.y 0..2) + Wo transpose
// (grid.y == 3). Outputs: q/k (n,s,h,d); v (n,h,d,s); g_wo [j][k].
// ---------------------------------------------------------------------------
__global__ void __launch_bounds__(128) proj_mma(
    const float* __restrict__ vals, const float* __restrict__ keys,
    const float* __restrict__ qry,
    const float* __restrict__ Wv, const float* __restrict__ Wk,
    const float* __restrict__ Wq, const float* __restrict__ Wo)
{
    __shared__ __align__(16) __half Xh[128 * 72];   // X tile [r][d]
    __shared__ __align__(16) __half Wh[64 * 72];    // W transposed [c][d]

    const int t = blockIdx.y;
    const int tid = threadIdx.x;

    if (t == 3) {   // Wo transpose slice: one 32x32 tile per block
        float* tf = (float*)Xh;     // 32 x 33 floats
        const int b = blockIdx.x;
        const int j0 = (b & 31) * 32, k0 = (b >> 5) * 32;
        const int tx = tid & 31, ty = tid >> 5;   // ty 0..3
#pragma unroll
        for (int i = 0; i < 8; i++)
            tf[(ty + 4 * i) * 33 + tx] = Wo[(size_t)(k0 + ty + 4 * i) * EMB + j0 + tx];
        __syncthreads();
#pragma unroll
        for (int i = 0; i < 8; i++)
            g_wo[(size_t)(j0 + ty + 4 * i) * EMB + k0 + tx] =
                __float2half_rn(tf[tx * 33 + ty + 4 * i]);
        return;
    }

    const float* X = (t == 0) ? vals : (t == 1) ? keys : qry;
    const float* W = (t == 0) ? Wv   : (t == 1) ? Wk   : Wq;
    const float scale = (t == 2) ? 0.03125f : 1.0f;

    const int wid = tid >> 5, lane = tid & 31;
    const int gp = lane >> 2, tg = lane & 3;
    const int g0 = blockIdx.x * 128;
    const int wr = wid * 32;

    for (int i = tid; i < 4096; i += 128) {
        int d = i >> 6, c = i & 63;
        Wh[c * 72 + d] = __float2half_rn(W[i]);
    }
    for (int idx = tid * 4; idx < 128 * 64; idx += 512) {
        int r = idx >> 6, d = idx & 63;
        float4 v = *(const float4*)&X[(g0 + r) * 64 + d];
        *(uint32_t*)&Xh[r * 72 + d]     = h2pack(v.x * scale, v.y * scale);
        *(uint32_t*)&Xh[r * 72 + d + 2] = h2pack(v.z * scale, v.w * scale);
    }
    __syncthreads();

    float acc[2][8][4] = {};
#pragma unroll
    for (int kc = 0; kc < 4; kc++) {
        const int k0 = kc * 16 + 2 * tg;
        uint32_t a[2][4];
#pragma unroll
        for (int mt = 0; mt < 2; mt++) {
            const int rr = wr + mt * 16 + gp;
            a[mt][0] = *(uint32_t*)&Xh[rr * 72 + k0];
            a[mt][1] = *(uint32_t*)&Xh[(rr + 8) * 72 + k0];
            a[mt][2] = *(uint32_t*)&Xh[rr * 72 + k0 + 8];
            a[mt][3] = *(uint32_t*)&Xh[(rr + 8) * 72 + k0 + 8];
        }
#pragma unroll
        for (int nt = 0; nt < 8; nt++) {
            const uint32_t b0 = *(uint32_t*)&Wh[(nt * 8 + gp) * 72 + k0];
            const uint32_t b1 = *(uint32_t*)&Wh[(nt * 8 + gp) * 72 + k0 + 8];
            mma_f16(acc[0][nt], a[0], b0, b1);
            mma_f16(acc[1][nt], a[1], b0, b1);
        }
    }
    __syncthreads();   // Xh free for epilogue reuse

    if (t != 0) {
        __half* out = (t == 1) ? g_k : g_q;
#pragma unroll
        for (int mt = 0; mt < 2; mt++) {
            const int rr = wr + mt * 16 + gp;
#pragma unroll
            for (int nt = 0; nt < 8; nt++) {
                const int c = nt * 8 + 2 * tg;
                *(uint32_t*)&Xh[rr * 72 + c]       = h2pack(acc[mt][nt][0], acc[mt][nt][1]);
                *(uint32_t*)&Xh[(rr + 8) * 72 + c] = h2pack(acc[mt][nt][2], acc[mt][nt][3]);
            }
        }
        __syncthreads();
        for (int i = tid; i < 1024; i += 128) {
            int r = i >> 3, c8 = (i & 7) * 8;
            *(uint4*)&out[(size_t)(g0 + r) * 64 + c8] = *(uint4*)&Xh[r * 72 + c8];
        }
    } else {
        __half* vsm = Xh;   // (h, d, s-local): 16*64*8 halves
#pragma unroll
        for (int mt = 0; mt < 2; mt++) {
#pragma unroll
            for (int nt = 0; nt < 8; nt++) {
                const int c = nt * 8 + 2 * tg;
                const int r0r = wr + mt * 16 + gp;
                const int r1r = r0r + 8;
                vsm[((r0r & 15) * 64 + c)     * 8 + (r0r >> 4)] = __float2half_rn(acc[mt][nt][0]);
                vsm[((r0r & 15) * 64 + c + 1) * 8 + (r0r >> 4)] = __float2half_rn(acc[mt][nt][1]);
                vsm[((r1r & 15) * 64 + c)     * 8 + (r1r >> 4)] = __float2half_rn(acc[mt][nt][2]);
                vsm[((r1r & 15) * 64 + c + 1) * 8 + (r1r >> 4)] = __float2half_rn(acc[mt][nt][3]);
            }
        }
        __syncthreads();
        const int n = g0 >> 15;
        const int s0 = (g0 >> 4) & (SEQ - 1);
        for (int i = tid; i < 1024; i += 128) {
            int h = i >> 6, d = i & 63;
            *(uint4*)&g_v[(size_t)((n * 16 + h) * 64 + d) * SEQ + s0] =
                *(uint4*)&vsm[(h * 64 + d) * 8];
        }
    }
}

// ---------------------------------------------------------------------------
// Kernel 2: flash attention, fp16 HMMA. 128 thr, 4 warps x 32 q-rows,
// 3 blocks/SM (mt-split halves live sf/pa regs). B-fragments via
// ldmatrix.x4 (4x fewer LSU issues). ex2.f16x2 softmax, MMA row-sums.
// ---------------------------------------------------------------------------
__global__ void __launch_bounds__(128, 3) flash_mma(const float* __restrict__ mask)
{
    __shared__ __align__(16) __half Kh[2 * 64 * 72];   // K bufs; Q staged here first
    __shared__ __align__(16) __half Vh[2 * 64 * 72];   // Vt bufs [d][s]
    __shared__ float msf[SEQ];                          // mask bias (log2-domain)

    const int tid = threadIdx.x;
    const int wid = tid >> 5, lane = tid & 31;
    const int gp = lane >> 2, tg = lane & 3;
    const int bh = blockIdx.y;
    const int n = bh >> 4, h = bh & 15;
    const int q0 = blockIdx.x * 128;
    const size_t base0 = ((size_t)n << 21) | (size_t)(h << 6);   // +s*1024+d
    const size_t vbase = (size_t)(n * 16 + h) * 64 * SEQ;        // +d*2048+s
    const float L2E = 1.4426950408889634f;

    const uint32_t sbK = smem_u32(Kh);
    const uint32_t sbV = smem_u32(Vh);
    // ldmatrix lane offset (bytes) for the n-major B tiles (stride 72 halves):
    // lanes 0-7: b0 rows of nt=2m; 8-15: b1 (col+8); 16-23: b0 of nt=2m+1; 24-31: b1.
    const uint32_t lmB2 = (((lane & 7) + ((lane & 16) >> 1)) * 72 + (lane & 8)) * 2;

    // stage Q (fills both K bufs: 128*72 halves)
    for (int i = tid; i < 1024; i += 128) {
        int r = i >> 3, c8 = (i & 7) * 8;
        cp16(sbK + (uint32_t)(r * 72 + c8) * 2u, g_q + base0 + (size_t)(q0 + r) * 1024 + c8);
    }
    CP_COMMIT();
    for (int i = tid; i < SEQ; i += 128)
        msf[i] = (mask[n * SEQ + i] == 0.0f) ? -1.0e4f : 0.0f;
    CP_WAIT0();
    __syncthreads();

    // Q fragments (m16n8k16 A): 4 k-chunks x 2 mt x 4 regs
    uint32_t qf[4][2][4];
#pragma unroll
    for (int kc = 0; kc < 4; kc++) {
        const int k0 = kc * 16 + 2 * tg;
#pragma unroll
        for (int mt = 0; mt < 2; mt++) {
            const int rr = wid * 32 + mt * 16 + gp;
            qf[kc][mt][0] = *(uint32_t*)&Kh[rr * 72 + k0];
            qf[kc][mt][1] = *(uint32_t*)&Kh[(rr + 8) * 72 + k0];
            qf[kc][mt][2] = *(uint32_t*)&Kh[rr * 72 + k0 + 8];
            qf[kc][mt][3] = *(uint32_t*)&Kh[(rr + 8) * 72 + k0 + 8];
        }
    }
    __syncthreads();

    // prefetch tile 0
    for (int i = tid; i < 1024; i += 128) {
        if (i < 512) {
            int r = i >> 3, c8 = (i & 7) * 8;
            cp16(sbK + (uint32_t)(r * 72 + c8) * 2u, g_k + base0 + (size_t)r * 1024 + c8);
        } else {
            int d = (i - 512) >> 3, s8 = ((i - 512) & 7) * 8;
            cp16(sbV + (uint32_t)(d * 72 + s8) * 2u, g_v + vbase + (size_t)d * SEQ + s8);
        }
    }
    CP_COMMIT();

    float ofrag[2][8][4] = {};
    float lacc[2][4] = {};        // row-sum accumulators (P @ ones)

    for (int kt = 0; kt < 32; kt++) {
        if (kt + 1 < 32) {
            const int buf = (kt + 1) & 1;
            for (int i = tid; i < 1024; i += 128) {
                if (i < 512) {
                    int r = i >> 3, c8 = (i & 7) * 8;
                    cp16(sbK + (uint32_t)(buf * 4608 + r * 72 + c8) * 2u,
                         g_k + base0 + (size_t)((kt + 1) * 64 + r) * 1024 + c8);
                } else {
                    int d = (i - 512) >> 3, s8 = ((i - 512) & 7) * 8;
                    cp16(sbV + (uint32_t)(buf * 4608 + d * 72 + s8) * 2u,
                         g_v + vbase + (size_t)d * SEQ + (kt + 1) * 64 + s8);
                }
            }
            CP_COMMIT();
            CP_WAIT1();
        } else {
            CP_WAIT0();
        }
        __syncthreads();

        const uint32_t kb = sbK + (kt & 1) * 9216 + lmB2;
        const uint32_t vb = sbV + (kt & 1) * 9216 + lmB2;

#pragma unroll
        for (int mt = 0; mt < 2; mt++) {
            // S = Q @ K^T  (16 x 64 per mt)
            float sfr[8][4] = {};
#pragma unroll
            for (int kc = 0; kc < 4; kc++) {
#pragma unroll
                for (int m = 0; m < 4; m++) {
                    uint32_t b0, b1, b2, b3;
                    ldm_x4(b0, b1, b2, b3, kb + m * 2304 + kc * 32);
                    mma_f16(sfr[2 * m],     qf[kc][mt], b0, b1);
                    mma_f16(sfr[2 * m + 1], qf[kc][mt], b2, b3);
                }
            }

            // softmax: t = s*log2e + bias; ex2.f16x2 -> PV A-fragments
            uint32_t pa[4][4];
#pragma unroll
            for (int nt = 0; nt < 8; nt++) {
                const int c0 = nt * 8 + 2 * tg;
                const float mb0 = msf[kt * 64 + c0];
                const float mb1 = msf[kt * 64 + c0 + 1];
                float t0 = fmaf(sfr[nt][0], L2E, mb0);
                float t1 = fmaf(sfr[nt][1], L2E, mb1);
                float t2 = fmaf(sfr[nt][2], L2E, mb0);
                float t3 = fmaf(sfr[nt][3], L2E, mb1);
                const int j = nt >> 1;
                if ((nt & 1) == 0) {
                    pa[j][0] = ex2h2(h2pack(t0, t1));
                    pa[j][1] = ex2h2(h2pack(t2, t3));
                } else {
                    pa[j][2] = ex2h2(h2pack(t0, t1));
                    pa[j][3] = ex2h2(h2pack(t2, t3));
                }
            }

            // O += P @ V ; row sums += P @ ones
#pragma unroll
            for (int j = 0; j < 4; j++) {
#pragma unroll
                for (int m = 0; m < 4; m++) {
                    uint32_t b0, b1, b2, b3;
                    ldm_x4(b0, b1, b2, b3, vb + m * 2304 + j * 32);
                    mma_f16(ofrag[mt][2 * m],     pa[j], b0, b1);
                    mma_f16(ofrag[mt][2 * m + 1], pa[j], b2, b3);
                }
                mma_f16(lacc[mt], pa[j], HALF2_ONES, HALF2_ONES);
            }
        }
        __syncthreads();   // all warps done with this K/V buffer
    }

    // epilogue: normalize -> half, per-warp smem transpose, linear 16B stores
    // lacc[mt][0] = rowsum(gp), lacc[mt][2] = rowsum(gp+8) (k-reduce spans tg)
    __half* aobuf = Kh + wid * 2304;   // 32 x 72 halves per warp
#pragma unroll
    for (int mt = 0; mt < 2; mt++) {
        const float inv0 = 1.0f / lacc[mt][0];
        const float inv1 = 1.0f / lacc[mt][2];
        const int rr = mt * 16 + gp;
#pragma unroll
        for (int nt = 0; nt < 8; nt++) {
            const int c = nt * 8 + 2 * tg;
            *(uint32_t*)&aobuf[rr * 72 + c] =
                h2pack(ofrag[mt][nt][0] * inv0, ofrag[mt][nt][1] * inv0);
            *(uint32_t*)&aobuf[(rr + 8) * 72 + c] =
                h2pack(ofrag[mt][nt][2] * inv1, ofrag[mt][nt][3] * inv1);
        }
    }
    __syncwarp();
    const size_t obase = (size_t)(n * SEQ + q0 + wid * 32) * 1024 + h * 64;
    for (int i = lane; i < 256; i += 32) {
        int r = i >> 3, c8 = (i & 7) * 8;
        *(uint4*)&g_ao[obase + (size_t)r * 1024 + c8] = *(uint4*)&aobuf[r * 72 + c8];
    }
}

// ---------------------------------------------------------------------------
// Kernel 3: out = g_ao @ Wo + bo on fp16 HMMA. 128 thr, 4 warps (2x2),
// warp tile 64x64, BK=32. ldmatrix.x4 for A and B fragments.
// ---------------------------------------------------------------------------
#define OG_SMEM 71680

__global__ void __launch_bounds__(128, 2) out_gemm(
    const float* __restrict__ bo, float* __restrict__ out)
{
    extern __shared__ __align__(16) char og[];
    __half* Ash = (__half*)og;            // [2][128][40]
    __half* Bsh = Ash + 10240;            // [2][128][40]

    const int tid = threadIdx.x;
    const int wid = tid >> 5, lane = tid & 31;
    const int gp = lane >> 2, tg = lane & 3;
    const int wr = (wid & 1) * 64;
    const int wc = (wid >> 1) * 64;
    const int j0 = blockIdx.x * 128;
    const int m0 = blockIdx.y * 128;

    const uint32_t sbA = smem_u32(Ash);
    const uint32_t sbB = smem_u32(Bsh);
    // A (m-major, stride 40): matrices {M(rr,k0),M(rr+8,k0),M(rr,k0+8),M(rr+8,k0+8)}
    const uint32_t lmA2 = ((lane & 15) * 40 + ((lane & 16) >> 1)) * 2;
    // B (n-major, stride 40): same scheme as flash
    const uint32_t lmB2 = (((lane & 7) + ((lane & 16) >> 1)) * 40 + (lane & 8)) * 2;

    float acc[4][8][4] = {};

    for (int i = tid; i < 1024; i += 128) {
        if (i < 512) {
            int r = i >> 2, c8 = (i & 3) * 8;
            cp16(sbA + (uint32_t)(r * 40 + c8) * 2u, g_ao + (size_t)(m0 + r) * 1024 + c8);
        } else {
            int r = (i - 512) >> 2, c8 = ((i - 512) & 3) * 8;
            cp16(sbB + (uint32_t)(r * 40 + c8) * 2u, g_wo + (size_t)(j0 + r) * 1024 + c8);
        }
    }
    CP_COMMIT();

    for (int kt = 0; kt < 32; kt++) {
        if (kt + 1 < 32) {
            const int buf = (kt + 1) & 1;
            const int k0g = (kt + 1) * 32;
            for (int i = tid; i < 1024; i += 128) {
                if (i < 512) {
                    int r = i >> 2, c8 = (i & 3) * 8;
                    cp16(sbA + (uint32_t)(buf * 5120 + r * 40 + c8) * 2u,
                         g_ao + (size_t)(m0 + r) * 1024 + k0g + c8);
                } else {
                    int r = (i - 512) >> 2, c8 = ((i - 512) & 3) * 8;
                    cp16(sbB + (uint32_t)(buf * 5120 + r * 40 + c8) * 2u,
                         g_wo + (size_t)(j0 + r) * 1024 + k0g + c8);
                }
            }
            CP_COMMIT();
            CP_WAIT1();
        } else {
            CP_WAIT0();
        }
        __syncthreads();

        const uint32_t abase = sbA + (kt & 1) * 10240 + (uint32_t)(wr * 40) * 2 + lmA2;
        const uint32_t bbase = sbB + (kt & 1) * 10240 + (uint32_t)(wc * 40) * 2 + lmB2;
#pragma unroll
        for (int kc = 0; kc < 2; kc++) {
            uint32_t a[4][4];
#pragma unroll
            for (int mt = 0; mt < 4; mt++)
                ldm_x4(a[mt][0], a[mt][1], a[mt][2], a[mt][3],
                       abase + mt * 1280 + kc * 32);
#pragma unroll
            for (int m = 0; m < 4; m++) {
                uint32_t b0, b1, b2, b3;
                ldm_x4(b0, b1, b2, b3, bbase + m * 1280 + kc * 32);
#pragma unroll
                for (int mt = 0; mt < 4; mt++) {
                    mma_f16(acc[mt][2 * m],     a[mt], b0, b1);
                    mma_f16(acc[mt][2 * m + 1], a[mt], b2, b3);
                }
            }
        }
        __syncthreads();
    }

    // epilogue: bias + smem-transpose per warp (64x68 f32), linear stores
    float* sf = (float*)og + wid * 4352;
#pragma unroll
    for (int mt = 0; mt < 4; mt++) {
        const int rr = mt * 16 + gp;
#pragma unroll
        for (int nt = 0; nt < 8; nt++) {
            const int cc = nt * 8 + 2 * tg;
            const float b0v = bo[j0 + wc + cc];
            const float b1v = bo[j0 + wc + cc + 1];
            sf[rr * 68 + cc]           = acc[mt][nt][0] + b0v;
            sf[rr * 68 + cc + 1]       = acc[mt][nt][1] + b1v;
            sf[(rr + 8) * 68 + cc]     = acc[mt][nt][2] + b0v;
            sf[(rr + 8) * 68 + cc + 1] = acc[mt][nt][3] + b1v;
        }
    }
    __syncwarp();
    const size_t obase = (size_t)(m0 + wr) * 1024 + j0 + wc;
    for (int i = lane; i < 1024; i += 32) {
        int r = i >> 4, c4 = (i & 15) * 4;
        *(float4*)&out[obase + (size_t)r * 1024 + c4] = *(float4*)&sf[r * 68 + c4];
    }
}

// ---------------------------------------------------------------------------
extern "C" void kernel_launch(void* const* d_in, const int* in_sizes, int n_in,
                              void* d_out, int out_size)
{
    const float* values = (const float*)d_in[0];
    const float* keys   = (const float*)d_in[1];
    const float* query  = (const float*)d_in[2];
    const float* mask   = (const float*)d_in[3];
    const float* Wv     = (const float*)d_in[4];
    const float* Wk     = (const float*)d_in[5];
    const float* Wq     = (const float*)d_in[6];
    const float* Wo     = (const float*)d_in[7];
    const float* bo     = (const float*)d_in[8];
    float* out = (float*)d_out;

    cudaFuncSetAttribute(out_gemm, cudaFuncAttributeMaxDynamicSharedMemorySize, OG_SMEM);

    // y=0..2: V/K/Q projections; y=3: Wo transpose (1024 tiles of 32x32)
    proj_mma<<<dim3(ROWS_TOT / 128, 4), 128>>>(values, keys, query, Wv, Wk, Wq, Wo);
    flash_mma<<<dim3(SEQ / 128, NH), 128>>>(mask);
    out_gemm<<<dim3(EMB / 128, (NB * SEQ) / 128), 128, OG_SMEM>>>(bo, out);
}

// round 15
// speedup vs baseline: 1.4028x; 1.0550x over previous
#include <cuda_runtime.h>
#include <cuda_fp16.h>
#include <cstdint>

// Fixed problem shape
#define NB   4
#define SEQ  2048
#define EMB  1024
#define HEADS 16
#define DH   64
#define NH   (NB * HEADS)
#define ROWS_TOT (NB * SEQ * HEADS)   // 131072

// Scratch (device globals), all fp16.
// g_q/g_k: (n,s,h,d). g_v: (n,h,d,s). g_ao: (n,q,h,d). g_wo: Wo transposed [j][k].
__device__ __half g_q[ROWS_TOT * DH];
__device__ __half g_k[ROWS_TOT * DH];
__device__ __half g_v[ROWS_TOT * DH];
__device__ __half g_ao[NB * SEQ * EMB];
__device__ __half g_wo[EMB * EMB];

#define HALF2_ONES 0x3C003C00u   // (1.0h, 1.0h)

// ===========================================================================
// helpers
// ===========================================================================
__device__ __forceinline__ uint32_t h2pack(float lo, float hi) {
    uint32_t r;
    asm("cvt.rn.f16x2.f32 %0, %1, %2;" : "=r"(r) : "f"(hi), "f"(lo));
    return r;
}
__device__ __forceinline__ uint32_t ex2h2(uint32_t x) {
    uint32_t r;
    asm("ex2.approx.f16x2 %0, %1;" : "=r"(r) : "r"(x));
    return r;
}
__device__ __forceinline__ void mma_f16(float* d, const uint32_t* a,
                                        uint32_t b0, uint32_t b1) {
    asm volatile(
        "mma.sync.aligned.m16n8k16.row.col.f32.f16.f16.f32 "
        "{%0,%1,%2,%3}, {%4,%5,%6,%7}, {%8,%9}, {%0,%1,%2,%3};"
        : "+f"(d[0]), "+f"(d[1]), "+f"(d[2]), "+f"(d[3])
        : "r"(a[0]), "r"(a[1]), "r"(a[2]), "r"(a[3]), "r"(b0), "r"(b1));
}
__device__ __forceinline__ void ldm_x4(uint32_t& r0, uint32_t& r1,
                                       uint32_t& r2, uint32_t& r3, uint32_t addr) {
    asm volatile("ldmatrix.sync.aligned.m8n8.x4.shared.b16 {%0,%1,%2,%3}, [%4];"
                 : "=r"(r0), "=r"(r1), "=r"(r2), "=r"(r3) : "r"(addr));
}
__device__ __forceinline__ uint32_t smem_u32(const void* p) {
    uint32_t a;
    asm("{ .reg .u64 t; cvta.to.shared.u64 t, %1; cvt.u32.u64 %0, t; }"
        : "=r"(a) : "l"(p));
    return a;
}
__device__ __forceinline__ void cp16(uint32_t dst, const void* src) {
    asm volatile("cp.async.cg.shared.global [%0], [%1], 16;"
                 :: "r"(dst), "l"(src) : "memory");
}
#define CP_COMMIT() asm volatile("cp.async.commit_group;" ::: "memory")
#define CP_WAIT0()  asm volatile("cp.async.wait_group 0;" ::: "memory")
#define CP_WAIT1()  asm volatile("cp.async.wait_group 1;" ::: "memory")

// ---------------------------------------------------------------------------
// Kernel 1: per-head projections (grid.y 0..2) + Wo transpose (grid.y == 3).
// SOFTWARE-PIPELINED: each block owns PROJ_TILES row-tiles; cp.async
// prefetches tile i+1's fp32 X-panel during tile i's convert/MMA/epilogue.
// Outputs: q/k (n,s,h,d); v (n,h,d,s); g_wo [j][k].
// ---------------------------------------------------------------------------
#define PROJ_TILES 8
#define PROJ_SMEM  (34816 + 18432 + 9216)   // Xf32 [128][68]f + Xh [128][72]h + Wh

__global__ void __launch_bounds__(128) proj_mma(
    const float* __restrict__ vals, const float* __restrict__ keys,
    const float* __restrict__ qry,
    const float* __restrict__ Wv, const float* __restrict__ Wk,
    const float* __restrict__ Wq, const float* __restrict__ Wo)
{
    extern __shared__ __align__(16) char psm[];
    float* Xf  = (float*)psm;                    // [128][68] fp32 staging
    __half* Xh = (__half*)(psm + 34816);         // [128][72] fp16 tile
    __half* Wh = (__half*)(psm + 53248);         // [64][72]  W transposed

    const int t = blockIdx.y;
    const int tid = threadIdx.x;

    if (t == 3) {   // Wo transpose: 8 tiles of 32x32 per block
        float* tf = (float*)psm;     // 32 x 33 floats
        const int tx = tid & 31, ty = tid >> 5;   // ty 0..3
        for (int it = 0; it < PROJ_TILES; it++) {
            const int b = blockIdx.x * PROJ_TILES + it;
            const int j0 = (b & 31) * 32, k0 = (b >> 5) * 32;
#pragma unroll
            for (int i = 0; i < 8; i++)
                tf[(ty + 4 * i) * 33 + tx] = Wo[(size_t)(k0 + ty + 4 * i) * EMB + j0 + tx];
            __syncthreads();
#pragma unroll
            for (int i = 0; i < 8; i++)
                g_wo[(size_t)(j0 + ty + 4 * i) * EMB + k0 + tx] =
                    __float2half_rn(tf[tx * 33 + ty + 4 * i]);
            __syncthreads();
        }
        return;
    }

    const float* X = (t == 0) ? vals : (t == 1) ? keys : qry;
    const float* W = (t == 0) ? Wv   : (t == 1) ? Wk   : Wq;
    const float scale = (t == 2) ? 0.03125f : 1.0f;

    const int wid = tid >> 5, lane = tid & 31;
    const int gp = lane >> 2, tg = lane & 3;
    const int wr = wid * 32;
    const uint32_t sbXf = smem_u32(Xf);
    const int gbase = blockIdx.x * PROJ_TILES * 128;

    // W tile once per block
    for (int i = tid; i < 4096; i += 128) {
        int d = i >> 6, c = i & 63;
        Wh[c * 72 + d] = __float2half_rn(W[i]);
    }
    // prefetch tile 0
    for (int i = tid; i < 2048; i += 128) {
        int r = i >> 4, c4 = (i & 15) * 4;
        cp16(sbXf + (uint32_t)(r * 68 + c4) * 4u, X + (size_t)(gbase + r) * 64 + c4);
    }
    CP_COMMIT();

    for (int it = 0; it < PROJ_TILES; it++) {
        const int g0 = gbase + it * 128;
        CP_WAIT0();
        __syncthreads();

        // convert fp32 -> fp16 tile (applies scale)
        for (int i = tid; i < 2048; i += 128) {
            int r = i >> 4, c4 = (i & 15) * 4;
            float4 v = *(const float4*)&Xf[r * 68 + c4];
            *(uint32_t*)&Xh[r * 72 + c4]     = h2pack(v.x * scale, v.y * scale);
            *(uint32_t*)&Xh[r * 72 + c4 + 2] = h2pack(v.z * scale, v.w * scale);
        }
        __syncthreads();

        // prefetch next tile (Xf32 free now)
        if (it + 1 < PROJ_TILES) {
            for (int i = tid; i < 2048; i += 128) {
                int r = i >> 4, c4 = (i & 15) * 4;
                cp16(sbXf + (uint32_t)(r * 68 + c4) * 4u,
                     X + (size_t)(g0 + 128 + r) * 64 + c4);
            }
            CP_COMMIT();
        }

        // MMA: 128x64 @ 64x64
        float acc[2][8][4] = {};
#pragma unroll
        for (int kc = 0; kc < 4; kc++) {
            const int k0 = kc * 16 + 2 * tg;
            uint32_t a[2][4];
#pragma unroll
            for (int mt = 0; mt < 2; mt++) {
                const int rr = wr + mt * 16 + gp;
                a[mt][0] = *(uint32_t*)&Xh[rr * 72 + k0];
                a[mt][1] = *(uint32_t*)&Xh[(rr + 8) * 72 + k0];
                a[mt][2] = *(uint32_t*)&Xh[rr * 72 + k0 + 8];
                a[mt][3] = *(uint32_t*)&Xh[(rr + 8) * 72 + k0 + 8];
            }
#pragma unroll
            for (int nt = 0; nt < 8; nt++) {
                const uint32_t b0 = *(uint32_t*)&Wh[(nt * 8 + gp) * 72 + k0];
                const uint32_t b1 = *(uint32_t*)&Wh[(nt * 8 + gp) * 72 + k0 + 8];
                mma_f16(acc[0][nt], a[0], b0, b1);
                mma_f16(acc[1][nt], a[1], b0, b1);
            }
        }
        __syncthreads();   // all fragment reads done; Xh reusable

        if (t != 0) {
            __half* out = (t == 1) ? g_k : g_q;
#pragma unroll
            for (int mt = 0; mt < 2; mt++) {
                const int rr = wr + mt * 16 + gp;
#pragma unroll
                for (int nt = 0; nt < 8; nt++) {
                    const int c = nt * 8 + 2 * tg;
                    *(uint32_t*)&Xh[rr * 72 + c]       = h2pack(acc[mt][nt][0], acc[mt][nt][1]);
                    *(uint32_t*)&Xh[(rr + 8) * 72 + c] = h2pack(acc[mt][nt][2], acc[mt][nt][3]);
                }
            }
            __syncthreads();
            for (int i = tid; i < 1024; i += 128) {
                int r = i >> 3, c8 = (i & 7) * 8;
                *(uint4*)&out[(size_t)(g0 + r) * 64 + c8] = *(uint4*)&Xh[r * 72 + c8];
            }
        } else {
            __half* vsm = Xh;   // (h, d, s-local): 16*64*8 halves
#pragma unroll
            for (int mt = 0; mt < 2; mt++) {
#pragma unroll
                for (int nt = 0; nt < 8; nt++) {
                    const int c = nt * 8 + 2 * tg;
                    const int r0r = wr + mt * 16 + gp;
                    const int r1r = r0r + 8;
                    vsm[((r0r & 15) * 64 + c)     * 8 + (r0r >> 4)] = __float2half_rn(acc[mt][nt][0]);
                    vsm[((r0r & 15) * 64 + c + 1) * 8 + (r0r >> 4)] = __float2half_rn(acc[mt][nt][1]);
                    vsm[((r1r & 15) * 64 + c)     * 8 + (r1r >> 4)] = __float2half_rn(acc[mt][nt][2]);
                    vsm[((r1r & 15) * 64 + c + 1) * 8 + (r1r >> 4)] = __float2half_rn(acc[mt][nt][3]);
                }
            }
            __syncthreads();
            const int n = g0 >> 15;
            const int s0 = (g0 >> 4) & (SEQ - 1);
            for (int i = tid; i < 1024; i += 128) {
                int h = i >> 6, d = i & 63;
                *(uint4*)&g_v[(size_t)((n * 16 + h) * 64 + d) * SEQ + s0] =
                    *(uint4*)&vsm[(h * 64 + d) * 8];
            }
        }
        __syncthreads();   // stores from Xh done before next convert overwrites
    }
}

// ---------------------------------------------------------------------------
// Kernel 2: flash attention, fp16 HMMA. 128 thr, 4 warps x 32 q-rows,
// 3 blocks/SM. B-fragments via ldmatrix.x4. ex2.f16x2 softmax, MMA row-sums.
// ---------------------------------------------------------------------------
__global__ void __launch_bounds__(128, 3) flash_mma(const float* __restrict__ mask)
{
    __shared__ __align__(16) __half Kh[2 * 64 * 72];   // K bufs; Q staged here first
    __shared__ __align__(16) __half Vh[2 * 64 * 72];   // Vt bufs [d][s]
    __shared__ float msf[SEQ];                          // mask bias (log2-domain)

    const int tid = threadIdx.x;
    const int wid = tid >> 5, lane = tid & 31;
    const int gp = lane >> 2, tg = lane & 3;
    const int bh = blockIdx.y;
    const int n = bh >> 4, h = bh & 15;
    const int q0 = blockIdx.x * 128;
    const size_t base0 = ((size_t)n << 21) | (size_t)(h << 6);   // +s*1024+d
    const size_t vbase = (size_t)(n * 16 + h) * 64 * SEQ;        // +d*2048+s
    const float L2E = 1.4426950408889634f;

    const uint32_t sbK = smem_u32(Kh);
    const uint32_t sbV = smem_u32(Vh);
    const uint32_t lmB2 = (((lane & 7) + ((lane & 16) >> 1)) * 72 + (lane & 8)) * 2;

    // stage Q (fills both K bufs: 128*72 halves)
    for (int i = tid; i < 1024; i += 128) {
        int r = i >> 3, c8 = (i & 7) * 8;
        cp16(sbK + (uint32_t)(r * 72 + c8) * 2u, g_q + base0 + (size_t)(q0 + r) * 1024 + c8);
    }
    CP_COMMIT();
    for (int i = tid; i < SEQ; i += 128)
        msf[i] = (mask[n * SEQ + i] == 0.0f) ? -1.0e4f : 0.0f;
    CP_WAIT0();
    __syncthreads();

    // Q fragments (m16n8k16 A): 4 k-chunks x 2 mt x 4 regs
    uint32_t qf[4][2][4];
#pragma unroll
    for (int kc = 0; kc < 4; kc++) {
        const int k0 = kc * 16 + 2 * tg;
#pragma unroll
        for (int mt = 0; mt < 2; mt++) {
            const int rr = wid * 32 + mt * 16 + gp;
            qf[kc][mt][0] = *(uint32_t*)&Kh[rr * 72 + k0];
            qf[kc][mt][1] = *(uint32_t*)&Kh[(rr + 8) * 72 + k0];
            qf[kc][mt][2] = *(uint32_t*)&Kh[rr * 72 + k0 + 8];
            qf[kc][mt][3] = *(uint32_t*)&Kh[(rr + 8) * 72 + k0 + 8];
        }
    }
    __syncthreads();

    // prefetch tile 0
    for (int i = tid; i < 1024; i += 128) {
        if (i < 512) {
            int r = i >> 3, c8 = (i & 7) * 8;
            cp16(sbK + (uint32_t)(r * 72 + c8) * 2u, g_k + base0 + (size_t)r * 1024 + c8);
        } else {
            int d = (i - 512) >> 3, s8 = ((i - 512) & 7) * 8;
            cp16(sbV + (uint32_t)(d * 72 + s8) * 2u, g_v + vbase + (size_t)d * SEQ + s8);
        }
    }
    CP_COMMIT();

    float ofrag[2][8][4] = {};
    float lacc[2][4] = {};        // row-sum accumulators (P @ ones)

    for (int kt = 0; kt < 32; kt++) {
        if (kt + 1 < 32) {
            const int buf = (kt + 1) & 1;
            for (int i = tid; i < 1024; i += 128) {
                if (i < 512) {
                    int r = i >> 3, c8 = (i & 7) * 8;
                    cp16(sbK + (uint32_t)(buf * 4608 + r * 72 + c8) * 2u,
                         g_k + base0 + (size_t)((kt + 1) * 64 + r) * 1024 + c8);
                } else {
                    int d = (i - 512) >> 3, s8 = ((i - 512) & 7) * 8;
                    cp16(sbV + (uint32_t)(buf * 4608 + d * 72 + s8) * 2u,
                         g_v + vbase + (size_t)d * SEQ + (kt + 1) * 64 + s8);
                }
            }
            CP_COMMIT();
            CP_WAIT1();
        } else {
            CP_WAIT0();
        }
        __syncthreads();

        const uint32_t kb = sbK + (kt & 1) * 9216 + lmB2;
        const uint32_t vb = sbV + (kt & 1) * 9216 + lmB2;

#pragma unroll
        for (int mt = 0; mt < 2; mt++) {
            // S = Q @ K^T  (16 x 64 per mt)
            float sfr[8][4] = {};
#pragma unroll
            for (int kc = 0; kc < 4; kc++) {
#pragma unroll
                for (int m = 0; m < 4; m++) {
                    uint32_t b0, b1, b2, b3;
                    ldm_x4(b0, b1, b2, b3, kb + m * 2304 + kc * 32);
                    mma_f16(sfr[2 * m],     qf[kc][mt], b0, b1);
                    mma_f16(sfr[2 * m + 1], qf[kc][mt], b2, b3);
                }
            }

            // softmax: t = s*log2e + bias; ex2.f16x2 -> PV A-fragments
            uint32_t pa[4][4];
#pragma unroll
            for (int nt = 0; nt < 8; nt++) {
                const int c0 = nt * 8 + 2 * tg;
                const float mb0 = msf[kt * 64 + c0];
                const float mb1 = msf[kt * 64 + c0 + 1];
                float t0 = fmaf(sfr[nt][0], L2E, mb0);
                float t1 = fmaf(sfr[nt][1], L2E, mb1);
                float t2 = fmaf(sfr[nt][2], L2E, mb0);
                float t3 = fmaf(sfr[nt][3], L2E, mb1);
                const int j = nt >> 1;
                if ((nt & 1) == 0) {
                    pa[j][0] = ex2h2(h2pack(t0, t1));
                    pa[j][1] = ex2h2(h2pack(t2, t3));
                } else {
                    pa[j][2] = ex2h2(h2pack(t0, t1));
                    pa[j][3] = ex2h2(h2pack(t2, t3));
                }
            }

            // O += P @ V ; row sums += P @ ones
#pragma unroll
            for (int j = 0; j < 4; j++) {
#pragma unroll
                for (int m = 0; m < 4; m++) {
                    uint32_t b0, b1, b2, b3;
                    ldm_x4(b0, b1, b2, b3, vb + m * 2304 + j * 32);
                    mma_f16(ofrag[mt][2 * m],     pa[j], b0, b1);
                    mma_f16(ofrag[mt][2 * m + 1], pa[j], b2, b3);
                }
                mma_f16(lacc[mt], pa[j], HALF2_ONES, HALF2_ONES);
            }
        }
        __syncthreads();   // all warps done with this K/V buffer
    }

    // epilogue: normalize -> half, per-warp smem transpose, linear 16B stores
    __half* aobuf = Kh + wid * 2304;   // 32 x 72 halves per warp
#pragma unroll
    for (int mt = 0; mt < 2; mt++) {
        const float inv0 = 1.0f / lacc[mt][0];
        const float inv1 = 1.0f / lacc[mt][2];
        const int rr = mt * 16 + gp;
#pragma unroll
        for (int nt = 0; nt < 8; nt++) {
            const int c = nt * 8 + 2 * tg;
            *(uint32_t*)&aobuf[rr * 72 + c] =
                h2pack(ofrag[mt][nt][0] * inv0, ofrag[mt][nt][1] * inv0);
            *(uint32_t*)&aobuf[(rr + 8) * 72 + c] =
                h2pack(ofrag[mt][nt][2] * inv1, ofrag[mt][nt][3] * inv1);
        }
    }
    __syncwarp();
    const size_t obase = (size_t)(n * SEQ + q0 + wid * 32) * 1024 + h * 64;
    for (int i = lane; i < 256; i += 32) {
        int r = i >> 3, c8 = (i & 7) * 8;
        *(uint4*)&g_ao[obase + (size_t)r * 1024 + c8] = *(uint4*)&aobuf[r * 72 + c8];
    }
}

// ---------------------------------------------------------------------------
// Kernel 3: out = g_ao @ Wo + bo on fp16 HMMA. 128 thr, 4 warps (2x2),
// warp tile 64x64, BK=32. ldmatrix.x4 for A and B fragments.
// ---------------------------------------------------------------------------
#define OG_SMEM 71680

__global__ void __launch_bounds__(128, 2) out_gemm(
    const float* __restrict__ bo, float* __restrict__ out)
{
    extern __shared__ __align__(16) char og[];
    __half* Ash = (__half*)og;            // [2][128][40]
    __half* Bsh = Ash + 10240;            // [2][128][40]

    const int tid = threadIdx.x;
    const int wid = tid >> 5, lane = tid & 31;
    const int gp = lane >> 2, tg = lane & 3;
    const int wr = (wid & 1) * 64;
    const int wc = (wid >> 1) * 64;
    const int j0 = blockIdx.x * 128;
    const int m0 = blockIdx.y * 128;

    const uint32_t sbA = smem_u32(Ash);
    const uint32_t sbB = smem_u32(Bsh);
    const uint32_t lmA2 = ((lane & 15) * 40 + ((lane & 16) >> 1)) * 2;
    const uint32_t lmB2 = (((lane & 7) + ((lane & 16) >> 1)) * 40 + (lane & 8)) * 2;

    float acc[4][8][4] = {};

    for (int i = tid; i < 1024; i += 128) {
        if (i < 512) {
            int r = i >> 2, c8 = (i & 3) * 8;
            cp16(sbA + (uint32_t)(r * 40 + c8) * 2u, g_ao + (size_t)(m0 + r) * 1024 + c8);
        } else {
            int r = (i - 512) >> 2, c8 = ((i - 512) & 3) * 8;
            cp16(sbB + (uint32_t)(r * 40 + c8) * 2u, g_wo + (size_t)(j0 + r) * 1024 + c8);
        }
    }
    CP_COMMIT();

    for (int kt = 0; kt < 32; kt++) {
        if (kt + 1 < 32) {
            const int buf = (kt + 1) & 1;
            const int k0g = (kt + 1) * 32;
            for (int i = tid; i < 1024; i += 128) {
                if (i < 512) {
                    int r = i >> 2, c8 = (i & 3) * 8;
                    cp16(sbA + (uint32_t)(buf * 5120 + r * 40 + c8) * 2u,
                         g_ao + (size_t)(m0 + r) * 1024 + k0g + c8);
                } else {
                    int r = (i - 512) >> 2, c8 = ((i - 512) & 3) * 8;
                    cp16(sbB + (uint32_t)(buf * 5120 + r * 40 + c8) * 2u,
                         g_wo + (size_t)(j0 + r) * 1024 + k0g + c8);
                }
            }
            CP_COMMIT();
            CP_WAIT1();
        } else {
            CP_WAIT0();
        }
        __syncthreads();

        const uint32_t abase = sbA + (kt & 1) * 10240 + (uint32_t)(wr * 40) * 2 + lmA2;
        const uint32_t bbase = sbB + (kt & 1) * 10240 + (uint32_t)(wc * 40) * 2 + lmB2;
#pragma unroll
        for (int kc = 0; kc < 2; kc++) {
            uint32_t a[4][4];
#pragma unroll
            for (int mt = 0; mt < 4; mt++)
                ldm_x4(a[mt][0], a[mt][1], a[mt][2], a[mt][3],
                       abase + mt * 1280 + kc * 32);
#pragma unroll
            for (int m = 0; m < 4; m++) {
                uint32_t b0, b1, b2, b3;
                ldm_x4(b0, b1, b2, b3, bbase + m * 1280 + kc * 32);
#pragma unroll
                for (int mt = 0; mt < 4; mt++) {
                    mma_f16(acc[mt][2 * m],     a[mt], b0, b1);
                    mma_f16(acc[mt][2 * m + 1], a[mt], b2, b3);
                }
            }
        }
        __syncthreads();
    }

    // epilogue: bias + smem-transpose per warp (64x68 f32), linear stores
    float* sf = (float*)og + wid * 4352;
#pragma unroll
    for (int mt = 0; mt < 4; mt++) {
        const int rr = mt * 16 + gp;
#pragma unroll
        for (int nt = 0; nt < 8; nt++) {
            const int cc = nt * 8 + 2 * tg;
            const float b0v = bo[j0 + wc + cc];
            const float b1v = bo[j0 + wc + cc + 1];
            sf[rr * 68 + cc]           = acc[mt][nt][0] + b0v;
            sf[rr * 68 + cc + 1]       = acc[mt][nt][1] + b1v;
            sf[(rr + 8) * 68 + cc]     = acc[mt][nt][2] + b0v;
            sf[(rr + 8) * 68 + cc + 1] = acc[mt][nt][3] + b1v;
        }
    }
    __syncwarp();
    const size_t obase = (size_t)(m0 + wr) * 1024 + j0 + wc;
    for (int i = lane; i < 1024; i += 32) {
        int r = i >> 4, c4 = (i & 15) * 4;
        *(float4*)&out[obase + (size_t)r * 1024 + c4] = *(float4*)&sf[r * 68 + c4];
    }
}

// ---------------------------------------------------------------------------
extern "C" void kernel_launch(void* const* d_in, const int* in_sizes, int n_in,
                              void* d_out, int out_size)
{
    const float* values = (const float*)d_in[0];
    const float* keys   = (const float*)d_in[1];
    const float* query  = (const float*)d_in[2];
    const float* mask   = (const float*)d_in[3];
    const float* Wv     = (const float*)d_in[4];
    const float* Wk     = (const float*)d_in[5];
    const float* Wq     = (const float*)d_in[6];
    const float* Wo     = (const float*)d_in[7];
    const float* bo     = (const float*)d_in[8];
    float* out = (float*)d_out;

    cudaFuncSetAttribute(proj_mma, cudaFuncAttributeMaxDynamicSharedMemorySize, PROJ_SMEM);
    cudaFuncSetAttribute(out_gemm, cudaFuncAttributeMaxDynamicSharedMemorySize, OG_SMEM);

    // y=0..2: V/K/Q projections (8 row-tiles/block); y=3: Wo transpose
    proj_mma<<<dim3(ROWS_TOT / (128 * PROJ_TILES), 4), 128, PROJ_SMEM>>>(
        values, keys, query, Wv, Wk, Wq, Wo);
    flash_mma<<<dim3(SEQ / 128, NH), 128>>>(mask);
    out_gemm<<<dim3(EMB / 128, (NB * SEQ) / 128), 128, OG_SMEM>>>(bo, out);
}